// round 8
// baseline (speedup 1.0000x reference)
#include <cuda_runtime.h>
#include <cuda_fp16.h>
#include <cstdint>

#define BB 8
#define TT 2048
#define CC 1024
#define HH 64
#define NQT 32
#define SPL 4

__device__ __align__(16) __half g_qh[BB*TT*HH];
__device__ __align__(16) __half g_ql[BB*TT*HH];
__device__ __align__(16) __half g_kh[BB*TT*HH];
__device__ __align__(16) __half g_vh[BB*TT*HH];
__device__ __align__(16) __half g_wt[192*CC];     // unused (kept layout parity)
__device__ __align__(16) __half g_wf[CC*200];     // fused fp16 W rows k, 192 cols (pad 200)
__device__ float g_pO[BB*NQT*SPL*64*64];
__device__ float g_pM[BB*NQT*SPL*64];
__device__ float g_pL[BB*NQT*SPL*64];

__device__ __forceinline__ uint32_t smaddr(const void* p) {
    return (uint32_t)__cvta_generic_to_shared(p);
}
__device__ __forceinline__ void ldsm4(uint32_t r[4], uint32_t a) {
    asm volatile("ldmatrix.sync.aligned.m8n8.x4.shared.b16 {%0,%1,%2,%3}, [%4];\n"
        : "=r"(r[0]), "=r"(r[1]), "=r"(r[2]), "=r"(r[3]) : "r"(a));
}
__device__ __forceinline__ void ldsm4t(uint32_t r[4], uint32_t a) {
    asm volatile("ldmatrix.sync.aligned.m8n8.x4.trans.shared.b16 {%0,%1,%2,%3}, [%4];\n"
        : "=r"(r[0]), "=r"(r[1]), "=r"(r[2]), "=r"(r[3]) : "r"(a));
}
__device__ __forceinline__ void mma16816(float d[4], const uint32_t a[4], const uint32_t b[2]) {
    asm volatile("mma.sync.aligned.m16n8k16.row.col.f32.f16.f16.f32 "
        "{%0,%1,%2,%3}, {%4,%5,%6,%7}, {%8,%9}, {%0,%1,%2,%3};\n"
        : "+f"(d[0]), "+f"(d[1]), "+f"(d[2]), "+f"(d[3])
        : "r"(a[0]), "r"(a[1]), "r"(a[2]), "r"(a[3]), "r"(b[0]), "r"(b[1]));
}
__device__ __forceinline__ uint32_t packh2(float a, float b) {
    __half2 h = __floats2half2_rn(a, b);
    return *reinterpret_cast<uint32_t*>(&h);
}
#define CPA16(dst, src) \
    asm volatile("cp.async.cg.shared.global [%0], [%1], 16;" :: "r"(dst), "l"(src))
#define CPA_COMMIT() asm volatile("cp.async.commit_group;")

// ---------------------------------------------------------------------------
// W prep: fuse Wk|Wq|Wv -> g_wf[k][192] fp16 (row pad 200)
// ---------------------------------------------------------------------------
__global__ void wprep_kernel(const float* __restrict__ Wk,
                             const float* __restrict__ Wq,
                             const float* __restrict__ Wv)
{
    int idx = blockIdx.x*256 + threadIdx.x;       // over 1024*192
    int k = idx / 192, n = idx % 192;
    int m = n >> 6, h = n & 63;
    const float* W = (m == 0) ? Wk : (m == 1) ? Wq : Wv;
    g_wf[(size_t)k*200 + n] = __float2half_rn(W[(size_t)k*HH + h]);
}

// ---------------------------------------------------------------------------
// Projection: [rows x 1024] x [1024 x 192]. 256 threads / 8 warps.
// A fragments built DIRECTLY in registers from gmem (fp32 -> fp16 hi/lo,
// 2-term compensated). W staged via cp.async double buffer, ldsm4t for B.
// wg = wid>>2 owns 96 cols; w4 = wid&3 owns 16 rows.
// smem: 2 bufs x [32][200] halfs = 25600 B
// ---------------------------------------------------------------------------
__device__ __forceinline__ void w_stage(__half* ws, int k0, int tid) {
    #pragma unroll
    for (int i = 0; i < 3; i++) {
        int j = tid + i*256;                      // 0..767
        int r = j / 24, c8 = (j % 24)*8;
        CPA16(smaddr(ws + r*200 + c8), &g_wf[(size_t)(k0 + r)*200 + c8]);
    }
}

__global__ __launch_bounds__(256, 2) void proj_kernel(const float* __restrict__ x,
                                                      int row_base)
{
    __shared__ __half ws[2][32*200];

    const int tid = threadIdx.x;
    const int wid = tid >> 5, lane = tid & 31;
    const int wg = wid >> 2, w4 = wid & 3;
    const int row0 = row_base + blockIdx.x * 64;
    const int g = lane >> 3, rl = lane & 7;

    const int ar = row0 + w4*16 + (lane >> 2);    // fragment rows ar, ar+8
    const int kb = (lane & 3)*2;

    float acc[12][4];
    #pragma unroll
    for (int j = 0; j < 12; j++)
        #pragma unroll
        for (int e = 0; e < 4; e++) acc[j][e] = 0.f;

    w_stage(ws[0], 0, tid);
    CPA_COMMIT();

    // x prefetch registers for chunk 0: [sub][frag] frag: (r,k),(r+8,k),(r,k+8),(r+8,k+8)
    float2 px[2][4];
    #pragma unroll
    for (int s = 0; s < 2; s++) {
        int k = s*16 + kb;
        px[s][0] = *(const float2*)&x[(size_t)ar*CC + k];
        px[s][1] = *(const float2*)&x[(size_t)(ar+8)*CC + k];
        px[s][2] = *(const float2*)&x[(size_t)ar*CC + k + 8];
        px[s][3] = *(const float2*)&x[(size_t)(ar+8)*CC + k + 8];
    }

    #pragma unroll 1
    for (int c = 0; c < 32; c++) {
        __syncthreads();                          // prev-iter readers done
        if (c + 1 < 32) {
            w_stage(ws[(c+1) & 1], (c+1)*32, tid);
            CPA_COMMIT();
            asm volatile("cp.async.wait_group 1;");
        } else {
            asm volatile("cp.async.wait_group 0;");
        }

        // convert prefetched x -> hi/lo fragments
        uint32_t ah[2][4], al[2][4];
        #pragma unroll
        for (int s = 0; s < 2; s++)
            #pragma unroll
            for (int f = 0; f < 4; f++) {
                float vx = px[s][f].x, vy = px[s][f].y;
                __half hx = __float2half_rn(vx), hy = __float2half_rn(vy);
                ah[s][f] = *(uint32_t*)&(const __half2&)__halves2half2(hx, hy);
                al[s][f] = packh2(vx - __half2float(hx), vy - __half2float(hy));
            }
        if (c + 1 < 32) {                         // prefetch next chunk's x
            int k0n = (c+1)*32;
            #pragma unroll
            for (int s = 0; s < 2; s++) {
                int k = k0n + s*16 + kb;
                px[s][0] = *(const float2*)&x[(size_t)ar*CC + k];
                px[s][1] = *(const float2*)&x[(size_t)(ar+8)*CC + k];
                px[s][2] = *(const float2*)&x[(size_t)ar*CC + k + 8];
                px[s][3] = *(const float2*)&x[(size_t)(ar+8)*CC + k + 8];
            }
        }
        __syncthreads();                          // W chunk c visible to all

        const __half* wb = ws[c & 1];
        #pragma unroll
        for (int s = 0; s < 2; s++) {
            int br = s*16 + (g & 1)*8 + rl;
            #pragma unroll
            for (int j = 0; j < 6; j++) {
                int bc = wg*96 + j*16 + (g >> 1)*8;
                uint32_t bh[4];
                ldsm4t(bh, smaddr(&wb[br*200 + bc]));
                mma16816(acc[2*j],   ah[s], bh);
                mma16816(acc[2*j],   al[s], bh);
                mma16816(acc[2*j+1], ah[s], bh + 2);
                mma16816(acc[2*j+1], al[s], bh + 2);
            }
        }
    }

    // epilogue: thread owns rows (w4*16 + lane>>2) (+8), col pairs per j/h
    const int rl4 = lane >> 2, q2 = (lane & 3)*2;
    #pragma unroll
    for (int j = 0; j < 6; j++) {
        #pragma unroll
        for (int h = 0; h < 2; h++) {
            int n = wg*96 + j*16 + h*8 + q2;
            int m = n >> 6, hc = n & 63;
            #pragma unroll
            for (int er = 0; er < 2; er++) {
                float v0 = acc[2*j+h][er*2], v1 = acc[2*j+h][er*2+1];
                size_t off = (size_t)(row0 + w4*16 + rl4 + er*8)*HH + hc;
                if (m == 2) {
                    *(__half2*)&g_vh[off] = __floats2half2_rn(v0, v1);
                } else if (m == 0) {
                    *(__half2*)&g_kh[off] = __floats2half2_rn(v0, v1);
                } else {
                    v0 *= 0.125f; v1 *= 0.125f;
                    __half h0 = __float2half_rn(v0), h1 = __float2half_rn(v1);
                    *(__half2*)&g_qh[off] = __halves2half2(h0, h1);
                    *(__half2*)&g_ql[off] = __halves2half2(
                        __float2half_rn(v0 - __half2float(h0)),
                        __float2half_rn(v1 - __half2float(h1)));
                }
            }
        }
    }
}

// ---------------------------------------------------------------------------
// Flash attention, split-KV (round-6 logic; b offset for phased launch)
// ---------------------------------------------------------------------------
#define ATT_SMEM_BYTES ((4608*2 + 2*9216) * 2)

__device__ __forceinline__ void kv_prefetch(__half* sh, int buf, size_t gbase,
                                            int tid)
{
    __half* base = sh + 9216 + buf*9216;
    #pragma unroll
    for (int i = 0; i < 8; i++) {
        int j = tid + i*128;
        int surf = j >> 9, rc = j & 511;
        int r = rc >> 3, c = (rc & 7)*8;
        CPA16(smaddr(base + surf*4608 + r*72 + c),
              (surf ? g_vh : g_kh) + gbase + r*64 + c);
    }
}

__global__ __launch_bounds__(128) void attn_kernel(int b0)
{
    extern __shared__ __half sh[];
    __half* Qh = sh;
    __half* Ql = sh + 4608;

    const int tid = threadIdx.x;
    const int w = tid >> 5, lane = tid & 31;
    const int qt = NQT - 1 - ((int)blockIdx.x >> 2);
    const int js = blockIdx.x & 3;
    const int b = blockIdx.y + b0;
    const int chunk = (b*NQT + qt)*SPL + js;
    float* po = g_pO + (size_t)chunk*4096;

    if (js > qt) {
        #pragma unroll
        for (int i = 0; i < 32; i++) po[tid + i*128] = 0.f;
        if (tid < 64) { g_pM[chunk*64 + tid] = -1e9f; g_pL[chunk*64 + tid] = 0.f; }
        return;
    }

    const size_t kvb = (size_t)b*TT*HH;
    kv_prefetch(sh, 0, kvb + (size_t)js*64*HH, tid);
    CPA_COMMIT();

    {
        const size_t qb = kvb + (size_t)qt*64*HH;
        #pragma unroll
        for (int i = 0; i < 4; i++) {
            int idx = tid + i*128; int r = idx >> 3, c = (idx & 7)*8;
            *(int4*)&Qh[r*72 + c] = *(const int4*)&g_qh[qb + r*64 + c];
            *(int4*)&Ql[r*72 + c] = *(const int4*)&g_ql[qb + r*64 + c];
        }
    }
    __syncthreads();

    uint32_t aqh[4][4], aql[4][4];
    #pragma unroll
    for (int kc = 0; kc < 4; kc++) {
        int r = w*16 + (lane & 15), c = kc*16 + ((lane >> 4) << 3);
        ldsm4(aqh[kc], smaddr(&Qh[r*72 + c]));
        ldsm4(aql[kc], smaddr(&Ql[r*72 + c]));
    }

    float o[8][4];
    #pragma unroll
    for (int nt = 0; nt < 8; nt++)
        #pragma unroll
        for (int e = 0; e < 4; e++) o[nt][e] = 0.f;
    float m0 = -1e9f, m1 = -1e9f, l0 = 0.f, l1 = 0.f;

    #pragma unroll 1
    for (int kt = js; kt <= qt; kt += SPL) {
        __syncthreads();
        if (kt + SPL <= qt) {
            kv_prefetch(sh, ((kt - js) >> 2 & 1) ^ 1,
                        kvb + (size_t)(kt + SPL)*64*HH, tid);
            CPA_COMMIT();
            asm volatile("cp.async.wait_group 1;");
        } else {
            asm volatile("cp.async.wait_group 0;");
        }
        __syncthreads();

        __half* Khp = sh + 9216 + ((kt - js) >> 2 & 1)*9216;
        __half* Vsp = Khp + 4608;

        float s[8][4];
        #pragma unroll
        for (int nt = 0; nt < 8; nt++)
            #pragma unroll
            for (int e = 0; e < 4; e++) s[nt][e] = 0.f;
        const int g = lane >> 3, rl8 = lane & 7;
        #pragma unroll
        for (int kc = 0; kc < 4; kc++) {
            #pragma unroll
            for (int jj = 0; jj < 4; jj++) {
                int r = jj*16 + (g >> 1)*8 + rl8;
                int ccol = kc*16 + (g & 1)*8;
                uint32_t bh[4];
                ldsm4(bh, smaddr(&Khp[r*72 + ccol]));
                mma16816(s[2*jj],   aqh[kc], bh);
                mma16816(s[2*jj],   aql[kc], bh);
                mma16816(s[2*jj+1], aqh[kc], bh + 2);
                mma16816(s[2*jj+1], aql[kc], bh + 2);
            }
        }

        if (kt == qt) {
            int r0l = w*16 + (lane >> 2);
            int c0l = (lane & 3)*2;
            #pragma unroll
            for (int nt = 0; nt < 8; nt++) {
                int c = nt*8 + c0l;
                if (c     > r0l)     s[nt][0] = -1e9f;
                if (c + 1 > r0l)     s[nt][1] = -1e9f;
                if (c     > r0l + 8) s[nt][2] = -1e9f;
                if (c + 1 > r0l + 8) s[nt][3] = -1e9f;
            }
        }

        float rm0 = -1e9f, rm1 = -1e9f;
        #pragma unroll
        for (int nt = 0; nt < 8; nt++) {
            rm0 = fmaxf(rm0, fmaxf(s[nt][0], s[nt][1]));
            rm1 = fmaxf(rm1, fmaxf(s[nt][2], s[nt][3]));
        }
        rm0 = fmaxf(rm0, __shfl_xor_sync(0xffffffffu, rm0, 1));
        rm0 = fmaxf(rm0, __shfl_xor_sync(0xffffffffu, rm0, 2));
        rm1 = fmaxf(rm1, __shfl_xor_sync(0xffffffffu, rm1, 1));
        rm1 = fmaxf(rm1, __shfl_xor_sync(0xffffffffu, rm1, 2));
        float mn0 = fmaxf(m0, rm0), mn1 = fmaxf(m1, rm1);
        float corr0 = __expf(m0 - mn0), corr1 = __expf(m1 - mn1);
        m0 = mn0; m1 = mn1;
        float rs0 = 0.f, rs1 = 0.f;
        #pragma unroll
        for (int nt = 0; nt < 8; nt++) {
            s[nt][0] = __expf(s[nt][0] - mn0); rs0 += s[nt][0];
            s[nt][1] = __expf(s[nt][1] - mn0); rs0 += s[nt][1];
            s[nt][2] = __expf(s[nt][2] - mn1); rs1 += s[nt][2];
            s[nt][3] = __expf(s[nt][3] - mn1); rs1 += s[nt][3];
        }
        rs0 += __shfl_xor_sync(0xffffffffu, rs0, 1);
        rs0 += __shfl_xor_sync(0xffffffffu, rs0, 2);
        rs1 += __shfl_xor_sync(0xffffffffu, rs1, 1);
        rs1 += __shfl_xor_sync(0xffffffffu, rs1, 2);
        l0 = l0*corr0 + rs0;
        l1 = l1*corr1 + rs1;
        #pragma unroll
        for (int nt = 0; nt < 8; nt++) {
            o[nt][0] *= corr0; o[nt][1] *= corr0;
            o[nt][2] *= corr1; o[nt][3] *= corr1;
        }

        #pragma unroll
        for (int kc = 0; kc < 4; kc++) {
            uint32_t ap[4];
            ap[0] = packh2(s[2*kc][0],   s[2*kc][1]);
            ap[1] = packh2(s[2*kc][2],   s[2*kc][3]);
            ap[2] = packh2(s[2*kc+1][0], s[2*kc+1][1]);
            ap[3] = packh2(s[2*kc+1][2], s[2*kc+1][3]);
            #pragma unroll
            for (int jj = 0; jj < 4; jj++) {
                int r = kc*16 + (g & 1)*8 + rl8;
                int ccol = jj*16 + (g >> 1)*8;
                uint32_t vb[4];
                ldsm4t(vb, smaddr(&Vsp[r*72 + ccol]));
                mma16816(o[2*jj],   ap, vb);
                mma16816(o[2*jj+1], ap, vb + 2);
            }
        }
    }

    const int r0 = w*16 + (lane >> 2);
    #pragma unroll
    for (int nt = 0; nt < 8; nt++) {
        int c = nt*8 + (lane & 3)*2;
        *(float2*)&po[r0*64 + c]     = make_float2(o[nt][0], o[nt][1]);
        *(float2*)&po[(r0+8)*64 + c] = make_float2(o[nt][2], o[nt][3]);
    }
    if ((lane & 3) == 0) {
        g_pM[chunk*64 + r0] = m0;  g_pL[chunk*64 + r0] = l0;
        g_pM[chunk*64 + r0+8] = m1; g_pL[chunk*64 + r0+8] = l1;
    }
}

// ---------------------------------------------------------------------------
// Merge: 1024 threads, thread = (row, float4 col group). Full MLP.
// ---------------------------------------------------------------------------
__global__ __launch_bounds__(1024) void merge_kernel(float* __restrict__ out, int b0)
{
    const int qt = blockIdx.x, b = blockIdx.y + b0;
    const int tid = threadIdx.x;
    const int r = tid >> 4, c4 = (tid & 15)*4;
    const int c0 = (b*NQT + qt)*SPL;

    float m[SPL], l[SPL];
    float M = -1e30f;
    #pragma unroll
    for (int j = 0; j < SPL; j++) {
        m[j] = g_pM[(c0 + j)*64 + r];
        l[j] = g_pL[(c0 + j)*64 + r];
        M = fmaxf(M, m[j]);
    }
    float wsum = 0.f, wj[SPL];
    #pragma unroll
    for (int j = 0; j < SPL; j++) {
        wj[j] = __expf(m[j] - M);
        wsum += wj[j]*l[j];
    }
    const float inv = 1.0f/wsum;

    float4 a = make_float4(0.f, 0.f, 0.f, 0.f);
    #pragma unroll
    for (int j = 0; j < SPL; j++) {
        float4 p = *(const float4*)&g_pO[(size_t)(c0 + j)*4096 + r*64 + c4];
        a.x += wj[j]*p.x; a.y += wj[j]*p.y;
        a.z += wj[j]*p.z; a.w += wj[j]*p.w;
    }
    a.x *= inv; a.y *= inv; a.z *= inv; a.w *= inv;
    *(float4*)&out[((size_t)b*TT + qt*64 + r)*HH + c4] = a;
}

extern "C" void kernel_launch(void* const* d_in, const int* in_sizes, int n_in,
                              void* d_out, int out_size) {
    const float* x  = (const float*)d_in[0];
    const float* Wk = (const float*)d_in[1];
    const float* Wq = (const float*)d_in[2];
    const float* Wv = (const float*)d_in[3];
    float* out = (float*)d_out;

    static int init = 0;
    static cudaStream_t s1;
    static cudaEvent_t eA, e1;
    if (!init) {
        cudaFuncSetAttribute(attn_kernel,
            cudaFuncAttributeMaxDynamicSharedMemorySize, ATT_SMEM_BYTES);
        cudaStreamCreateWithFlags(&s1, cudaStreamNonBlocking);
        cudaEventCreateWithFlags(&eA, cudaEventDisableTiming);
        cudaEventCreateWithFlags(&e1, cudaEventDisableTiming);
        init = 1;
    }

    wprep_kernel<<<768, 256>>>(Wk, Wq, Wv);
    proj_kernel<<<128, 256>>>(x, 0);          // batches 0-3
    cudaEventRecord(eA, 0);
    proj_kernel<<<128, 256>>>(x, 4*TT);       // batches 4-7 (on stream 0)

    cudaStreamWaitEvent(s1, eA, 0);           // fork: attn 0-3 overlaps proj 4-7
    attn_kernel<<<dim3(NQT*SPL, 4), 128, ATT_SMEM_BYTES, s1>>>(0);
    merge_kernel<<<dim3(NQT, 4), 1024, 0, s1>>>(out, 0);
    cudaEventRecord(e1, s1);

    attn_kernel<<<dim3(NQT*SPL, 4), 128, ATT_SMEM_BYTES>>>(4);
    merge_kernel<<<dim3(NQT, 4), 1024>>>(out, 4);
    cudaStreamWaitEvent(0, e1, 0);            // join
}

// round 9
// speedup vs baseline: 1.1052x; 1.1052x over previous
#include <cuda_runtime.h>
#include <cuda_fp16.h>
#include <cstdint>

#define BB 8
#define TT 2048
#define CC 1024
#define HH 64
#define NQT 32
#define SPL 4

__device__ __align__(16) __half g_qh[BB*TT*HH];
__device__ __align__(16) __half g_ql[BB*TT*HH];
__device__ __align__(16) __half g_kh[BB*TT*HH];
__device__ __align__(16) __half g_vh[BB*TT*HH];
__device__ __align__(16) __half g_wf[CC*200];     // fused fp16 W rows k, 192 cols (pad 200)
__device__ float g_pO[BB*NQT*SPL*64*64];
__device__ float g_pM[BB*NQT*SPL*64];
__device__ float g_pL[BB*NQT*SPL*64];

__device__ __forceinline__ uint32_t smaddr(const void* p) {
    return (uint32_t)__cvta_generic_to_shared(p);
}
__device__ __forceinline__ void ldsm4(uint32_t r[4], uint32_t a) {
    asm volatile("ldmatrix.sync.aligned.m8n8.x4.shared.b16 {%0,%1,%2,%3}, [%4];\n"
        : "=r"(r[0]), "=r"(r[1]), "=r"(r[2]), "=r"(r[3]) : "r"(a));
}
__device__ __forceinline__ void ldsm4t(uint32_t r[4], uint32_t a) {
    asm volatile("ldmatrix.sync.aligned.m8n8.x4.trans.shared.b16 {%0,%1,%2,%3}, [%4];\n"
        : "=r"(r[0]), "=r"(r[1]), "=r"(r[2]), "=r"(r[3]) : "r"(a));
}
__device__ __forceinline__ void mma16816(float d[4], const uint32_t a[4], const uint32_t b[2]) {
    asm volatile("mma.sync.aligned.m16n8k16.row.col.f32.f16.f16.f32 "
        "{%0,%1,%2,%3}, {%4,%5,%6,%7}, {%8,%9}, {%0,%1,%2,%3};\n"
        : "+f"(d[0]), "+f"(d[1]), "+f"(d[2]), "+f"(d[3])
        : "r"(a[0]), "r"(a[1]), "r"(a[2]), "r"(a[3]), "r"(b[0]), "r"(b[1]));
}
__device__ __forceinline__ uint32_t packh2(float a, float b) {
    __half2 h = __floats2half2_rn(a, b);
    return *reinterpret_cast<uint32_t*>(&h);
}
#define CPA16(dst, src) \
    asm volatile("cp.async.cg.shared.global [%0], [%1], 16;" :: "r"(dst), "l"(src))
#define CPA_COMMIT() asm volatile("cp.async.commit_group;")

// ---------------------------------------------------------------------------
// W prep: fuse Wk|Wq|Wv -> g_wf[k][192] fp16 (row pad 200)
// ---------------------------------------------------------------------------
__global__ void wprep_kernel(const float* __restrict__ Wk,
                             const float* __restrict__ Wq,
                             const float* __restrict__ Wv)
{
    int idx = blockIdx.x*256 + threadIdx.x;       // over 1024*192
    int k = idx / 192, n = idx % 192;
    int m = n >> 6, h = n & 63;
    const float* W = (m == 0) ? Wk : (m == 1) ? Wq : Wv;
    g_wf[(size_t)k*200 + n] = __float2half_rn(W[(size_t)k*HH + h]);
}

// ---------------------------------------------------------------------------
// Projection: [16384 x 1024] x [1024 x 192]. 256 CTAs x 64 rows, 256 thr.
// x: coalesced float4 LDG -> reg convert -> single STS hi/lo pass (pipelined).
// W: cp.async double buffer. 2 barriers per 32-K chunk.
// smem: xs hi/lo 2 bufs (20480 B) + ws 2 bufs (25600 B) = 46080 B (static).
// ---------------------------------------------------------------------------
__device__ __forceinline__ void w_stage(__half* ws, int k0, int tid) {
    #pragma unroll
    for (int i = 0; i < 3; i++) {
        int j = tid + i*256;                      // 0..767 = 32 rows x 24 groups
        int r = j / 24, c8 = (j % 24)*8;
        CPA16(smaddr(ws + r*200 + c8), &g_wf[(size_t)(k0 + r)*200 + c8]);
    }
}

__global__ __launch_bounds__(256, 2) void proj_kernel(const float* __restrict__ x)
{
    __shared__ __half xsh[2][64][40];
    __shared__ __half xsl[2][64][40];
    __shared__ __half ws[2][32*200];

    const int tid = threadIdx.x;
    const int wid = tid >> 5, lane = tid & 31;
    const int wg = wid >> 2, w4 = wid & 3;
    const int row0 = blockIdx.x * 64;
    const int g = lane >> 3, rl = lane & 7;
    const int pr = tid >> 3;                      // 0..31 (x load row)
    const int pc = (tid & 7)*4;                   // 0..28 (x load col4)

    float acc[12][4];
    #pragma unroll
    for (int j = 0; j < 12; j++)
        #pragma unroll
        for (int e = 0; e < 4; e++) acc[j][e] = 0.f;

    w_stage(ws[0], 0, tid);
    CPA_COMMIT();
    float4 px0 = *(const float4*)&x[(size_t)(row0 + pr)*CC + pc];
    float4 px1 = *(const float4*)&x[(size_t)(row0 + pr + 32)*CC + pc];

    #pragma unroll 1
    for (int c = 0; c < 32; c++) {
        const int buf = c & 1;
        __syncthreads();                          // everyone done with chunk c-1
        {   // STS chunk c from registers (hi/lo split)
            __half hx0 = __float2half_rn(px0.x), hy0 = __float2half_rn(px0.y);
            __half hz0 = __float2half_rn(px0.z), hw0 = __float2half_rn(px0.w);
            *(uint2*)&xsh[buf][pr][pc] = make_uint2(
                *(uint32_t*)&(const __half2&)__halves2half2(hx0, hy0),
                *(uint32_t*)&(const __half2&)__halves2half2(hz0, hw0));
            *(uint2*)&xsl[buf][pr][pc] = make_uint2(
                packh2(px0.x - __half2float(hx0), px0.y - __half2float(hy0)),
                packh2(px0.z - __half2float(hz0), px0.w - __half2float(hw0)));
            __half hx1 = __float2half_rn(px1.x), hy1 = __float2half_rn(px1.y);
            __half hz1 = __float2half_rn(px1.z), hw1 = __float2half_rn(px1.w);
            *(uint2*)&xsh[buf][pr+32][pc] = make_uint2(
                *(uint32_t*)&(const __half2&)__halves2half2(hx1, hy1),
                *(uint32_t*)&(const __half2&)__halves2half2(hz1, hw1));
            *(uint2*)&xsl[buf][pr+32][pc] = make_uint2(
                packh2(px1.x - __half2float(hx1), px1.y - __half2float(hy1)),
                packh2(px1.z - __half2float(hz1), px1.w - __half2float(hw1)));
        }
        if (c + 1 < 32) {
            w_stage(ws[buf ^ 1], (c+1)*32, tid);
            CPA_COMMIT();
            int k0n = (c+1)*32;
            px0 = *(const float4*)&x[(size_t)(row0 + pr)*CC + k0n + pc];
            px1 = *(const float4*)&x[(size_t)(row0 + pr + 32)*CC + k0n + pc];
            asm volatile("cp.async.wait_group 1;");
        } else {
            asm volatile("cp.async.wait_group 0;");
        }
        __syncthreads();                          // chunk c staged (xs + ws)

        const __half* wb = ws[buf];
        #pragma unroll
        for (int sub = 0; sub < 2; sub++) {
            uint32_t ah[4], al[4];
            int ar = w4*16 + (lane & 15), ac = sub*16 + ((lane >> 4) << 3);
            ldsm4(ah, smaddr(&xsh[buf][ar][ac]));
            ldsm4(al, smaddr(&xsl[buf][ar][ac]));
            int br = sub*16 + (g & 1)*8 + rl;
            #pragma unroll
            for (int j = 0; j < 6; j++) {
                int bc = wg*96 + j*16 + (g >> 1)*8;
                uint32_t bh[4];
                ldsm4t(bh, smaddr(&wb[br*200 + bc]));
                mma16816(acc[2*j],   ah, bh);
                mma16816(acc[2*j],   al, bh);
                mma16816(acc[2*j+1], ah, bh + 2);
                mma16816(acc[2*j+1], al, bh + 2);
            }
        }
    }

    // epilogue
    const int rl4 = lane >> 2, q2 = (lane & 3)*2;
    #pragma unroll
    for (int j = 0; j < 6; j++) {
        #pragma unroll
        for (int h = 0; h < 2; h++) {
            int n = wg*96 + j*16 + h*8 + q2;
            int m = n >> 6, hc = n & 63;
            #pragma unroll
            for (int er = 0; er < 2; er++) {
                float v0 = acc[2*j+h][er*2], v1 = acc[2*j+h][er*2+1];
                size_t off = (size_t)(row0 + w4*16 + rl4 + er*8)*HH + hc;
                if (m == 2) {
                    *(__half2*)&g_vh[off] = __floats2half2_rn(v0, v1);
                } else if (m == 0) {
                    *(__half2*)&g_kh[off] = __floats2half2_rn(v0, v1);
                } else {
                    v0 *= 0.125f; v1 *= 0.125f;
                    __half h0 = __float2half_rn(v0), h1 = __float2half_rn(v1);
                    *(__half2*)&g_qh[off] = __halves2half2(h0, h1);
                    *(__half2*)&g_ql[off] = __halves2half2(
                        __float2half_rn(v0 - __half2float(h0)),
                        __float2half_rn(v1 - __half2float(h1)));
                }
            }
        }
    }
}

// ---------------------------------------------------------------------------
// Flash attention, split-KV: CTA (qt, js) does kt = js, js+SPL, ... <= qt.
// ---------------------------------------------------------------------------
#define ATT_SMEM_BYTES ((4608*2 + 2*9216) * 2)

__device__ __forceinline__ void kv_prefetch(__half* sh, int buf, size_t gbase,
                                            int tid)
{
    __half* base = sh + 9216 + buf*9216;
    #pragma unroll
    for (int i = 0; i < 8; i++) {
        int j = tid + i*128;
        int surf = j >> 9, rc = j & 511;
        int r = rc >> 3, c = (rc & 7)*8;
        CPA16(smaddr(base + surf*4608 + r*72 + c),
              (surf ? g_vh : g_kh) + gbase + r*64 + c);
    }
}

__global__ __launch_bounds__(128) void attn_kernel()
{
    extern __shared__ __half sh[];
    __half* Qh = sh;
    __half* Ql = sh + 4608;

    const int tid = threadIdx.x;
    const int w = tid >> 5, lane = tid & 31;
    const int qt = NQT - 1 - ((int)blockIdx.x >> 2);
    const int js = blockIdx.x & 3;
    const int b = blockIdx.y;
    const int chunk = (b*NQT + qt)*SPL + js;
    float* po = g_pO + (size_t)chunk*4096;

    if (js > qt) {
        #pragma unroll
        for (int i = 0; i < 32; i++) po[tid + i*128] = 0.f;
        if (tid < 64) { g_pM[chunk*64 + tid] = -1e9f; g_pL[chunk*64 + tid] = 0.f; }
        return;
    }

    const size_t kvb = (size_t)b*TT*HH;
    kv_prefetch(sh, 0, kvb + (size_t)js*64*HH, tid);
    CPA_COMMIT();

    {
        const size_t qb = kvb + (size_t)qt*64*HH;
        #pragma unroll
        for (int i = 0; i < 4; i++) {
            int idx = tid + i*128; int r = idx >> 3, c = (idx & 7)*8;
            *(int4*)&Qh[r*72 + c] = *(const int4*)&g_qh[qb + r*64 + c];
            *(int4*)&Ql[r*72 + c] = *(const int4*)&g_ql[qb + r*64 + c];
        }
    }
    __syncthreads();

    uint32_t aqh[4][4], aql[4][4];
    #pragma unroll
    for (int kc = 0; kc < 4; kc++) {
        int r = w*16 + (lane & 15), c = kc*16 + ((lane >> 4) << 3);
        ldsm4(aqh[kc], smaddr(&Qh[r*72 + c]));
        ldsm4(aql[kc], smaddr(&Ql[r*72 + c]));
    }

    float o[8][4];
    #pragma unroll
    for (int nt = 0; nt < 8; nt++)
        #pragma unroll
        for (int e = 0; e < 4; e++) o[nt][e] = 0.f;
    float m0 = -1e9f, m1 = -1e9f, l0 = 0.f, l1 = 0.f;

    #pragma unroll 1
    for (int kt = js; kt <= qt; kt += SPL) {
        __syncthreads();
        if (kt + SPL <= qt) {
            kv_prefetch(sh, ((kt - js) >> 2 & 1) ^ 1,
                        kvb + (size_t)(kt + SPL)*64*HH, tid);
            CPA_COMMIT();
            asm volatile("cp.async.wait_group 1;");
        } else {
            asm volatile("cp.async.wait_group 0;");
        }
        __syncthreads();

        __half* Khp = sh + 9216 + ((kt - js) >> 2 & 1)*9216;
        __half* Vsp = Khp + 4608;

        float s[8][4];
        #pragma unroll
        for (int nt = 0; nt < 8; nt++)
            #pragma unroll
            for (int e = 0; e < 4; e++) s[nt][e] = 0.f;
        const int g = lane >> 3, rl8 = lane & 7;
        #pragma unroll
        for (int kc = 0; kc < 4; kc++) {
            #pragma unroll
            for (int jj = 0; jj < 4; jj++) {
                int r = jj*16 + (g >> 1)*8 + rl8;
                int ccol = kc*16 + (g & 1)*8;
                uint32_t bh[4];
                ldsm4(bh, smaddr(&Khp[r*72 + ccol]));
                mma16816(s[2*jj],   aqh[kc], bh);
                mma16816(s[2*jj],   aql[kc], bh);
                mma16816(s[2*jj+1], aqh[kc], bh + 2);
                mma16816(s[2*jj+1], aql[kc], bh + 2);
            }
        }

        if (kt == qt) {
            int r0l = w*16 + (lane >> 2);
            int c0l = (lane & 3)*2;
            #pragma unroll
            for (int nt = 0; nt < 8; nt++) {
                int c = nt*8 + c0l;
                if (c     > r0l)     s[nt][0] = -1e9f;
                if (c + 1 > r0l)     s[nt][1] = -1e9f;
                if (c     > r0l + 8) s[nt][2] = -1e9f;
                if (c + 1 > r0l + 8) s[nt][3] = -1e9f;
            }
        }

        float rm0 = -1e9f, rm1 = -1e9f;
        #pragma unroll
        for (int nt = 0; nt < 8; nt++) {
            rm0 = fmaxf(rm0, fmaxf(s[nt][0], s[nt][1]));
            rm1 = fmaxf(rm1, fmaxf(s[nt][2], s[nt][3]));
        }
        rm0 = fmaxf(rm0, __shfl_xor_sync(0xffffffffu, rm0, 1));
        rm0 = fmaxf(rm0, __shfl_xor_sync(0xffffffffu, rm0, 2));
        rm1 = fmaxf(rm1, __shfl_xor_sync(0xffffffffu, rm1, 1));
        rm1 = fmaxf(rm1, __shfl_xor_sync(0xffffffffu, rm1, 2));
        float mn0 = fmaxf(m0, rm0), mn1 = fmaxf(m1, rm1);
        float corr0 = __expf(m0 - mn0), corr1 = __expf(m1 - mn1);
        m0 = mn0; m1 = mn1;
        float rs0 = 0.f, rs1 = 0.f;
        #pragma unroll
        for (int nt = 0; nt < 8; nt++) {
            s[nt][0] = __expf(s[nt][0] - mn0); rs0 += s[nt][0];
            s[nt][1] = __expf(s[nt][1] - mn0); rs0 += s[nt][1];
            s[nt][2] = __expf(s[nt][2] - mn1); rs1 += s[nt][2];
            s[nt][3] = __expf(s[nt][3] - mn1); rs1 += s[nt][3];
        }
        rs0 += __shfl_xor_sync(0xffffffffu, rs0, 1);
        rs0 += __shfl_xor_sync(0xffffffffu, rs0, 2);
        rs1 += __shfl_xor_sync(0xffffffffu, rs1, 1);
        rs1 += __shfl_xor_sync(0xffffffffu, rs1, 2);
        l0 = l0*corr0 + rs0;
        l1 = l1*corr1 + rs1;
        #pragma unroll
        for (int nt = 0; nt < 8; nt++) {
            o[nt][0] *= corr0; o[nt][1] *= corr0;
            o[nt][2] *= corr1; o[nt][3] *= corr1;
        }

        #pragma unroll
        for (int kc = 0; kc < 4; kc++) {
            uint32_t ap[4];
            ap[0] = packh2(s[2*kc][0],   s[2*kc][1]);
            ap[1] = packh2(s[2*kc][2],   s[2*kc][3]);
            ap[2] = packh2(s[2*kc+1][0], s[2*kc+1][1]);
            ap[3] = packh2(s[2*kc+1][2], s[2*kc+1][3]);
            #pragma unroll
            for (int jj = 0; jj < 4; jj++) {
                int r = kc*16 + (g & 1)*8 + rl8;
                int ccol = jj*16 + (g >> 1)*8;
                uint32_t vb[4];
                ldsm4t(vb, smaddr(&Vsp[r*72 + ccol]));
                mma16816(o[2*jj],   ap, vb);
                mma16816(o[2*jj+1], ap, vb + 2);
            }
        }
    }

    const int r0 = w*16 + (lane >> 2);
    #pragma unroll
    for (int nt = 0; nt < 8; nt++) {
        int c = nt*8 + (lane & 3)*2;
        *(float2*)&po[r0*64 + c]     = make_float2(o[nt][0], o[nt][1]);
        *(float2*)&po[(r0+8)*64 + c] = make_float2(o[nt][2], o[nt][3]);
    }
    if ((lane & 3) == 0) {
        g_pM[chunk*64 + r0] = m0;  g_pL[chunk*64 + r0] = l0;
        g_pM[chunk*64 + r0+8] = m1; g_pL[chunk*64 + r0+8] = l1;
    }
}

// ---------------------------------------------------------------------------
// Merge: 1024 threads, thread = (row, float4 col group).
// ---------------------------------------------------------------------------
__global__ __launch_bounds__(1024) void merge_kernel(float* __restrict__ out)
{
    const int qt = blockIdx.x, b = blockIdx.y;
    const int tid = threadIdx.x;
    const int r = tid >> 4, c4 = (tid & 15)*4;
    const int c0 = (b*NQT + qt)*SPL;

    float m[SPL], l[SPL];
    float M = -1e30f;
    #pragma unroll
    for (int j = 0; j < SPL; j++) {
        m[j] = g_pM[(c0 + j)*64 + r];
        l[j] = g_pL[(c0 + j)*64 + r];
        M = fmaxf(M, m[j]);
    }
    float wsum = 0.f, wj[SPL];
    #pragma unroll
    for (int j = 0; j < SPL; j++) {
        wj[j] = __expf(m[j] - M);
        wsum += wj[j]*l[j];
    }
    const float inv = 1.0f/wsum;

    float4 a = make_float4(0.f, 0.f, 0.f, 0.f);
    #pragma unroll
    for (int j = 0; j < SPL; j++) {
        float4 p = *(const float4*)&g_pO[(size_t)(c0 + j)*4096 + r*64 + c4];
        a.x += wj[j]*p.x; a.y += wj[j]*p.y;
        a.z += wj[j]*p.z; a.w += wj[j]*p.w;
    }
    a.x *= inv; a.y *= inv; a.z *= inv; a.w *= inv;
    *(float4*)&out[((size_t)b*TT + qt*64 + r)*HH + c4] = a;
}

extern "C" void kernel_launch(void* const* d_in, const int* in_sizes, int n_in,
                              void* d_out, int out_size) {
    const float* x  = (const float*)d_in[0];
    const float* Wk = (const float*)d_in[1];
    const float* Wq = (const float*)d_in[2];
    const float* Wv = (const float*)d_in[3];
    float* out = (float*)d_out;

    static int init = 0;
    if (!init) {
        cudaFuncSetAttribute(attn_kernel,
            cudaFuncAttributeMaxDynamicSharedMemorySize, ATT_SMEM_BYTES);
        init = 1;
    }

    wprep_kernel<<<768, 256>>>(Wk, Wq, Wv);
    proj_kernel<<<(BB*TT)/64, 256>>>(x);
    attn_kernel<<<dim3(NQT*SPL, BB), 128, ATT_SMEM_BYTES>>>();
    merge_kernel<<<dim3(NQT, BB), 1024>>>(out);
}

// round 10
// speedup vs baseline: 1.1293x; 1.0218x over previous
#include <cuda_runtime.h>
#include <cuda_fp16.h>
#include <cstdint>

#define BB 8
#define TT 2048
#define CC 1024
#define HH 64
#define NQT 32
#define SPL 4

__device__ __align__(16) __half g_qh[BB*TT*HH];
__device__ __align__(16) __half g_ql[BB*TT*HH];
__device__ __align__(16) __half g_kh[BB*TT*HH];
__device__ __align__(16) __half g_vh[BB*TT*HH];
__device__ __align__(16) __half g_wf[CC*200];     // fused fp16 W rows k, 192 cols (pad 200)
__device__ float  g_pO[BB*NQT*SPL*64*64];
__device__ float2 g_pML[BB*NQT*SPL*64];           // (m, l) packed

__device__ __forceinline__ uint32_t smaddr(const void* p) {
    return (uint32_t)__cvta_generic_to_shared(p);
}
__device__ __forceinline__ void ldsm4(uint32_t r[4], uint32_t a) {
    asm volatile("ldmatrix.sync.aligned.m8n8.x4.shared.b16 {%0,%1,%2,%3}, [%4];\n"
        : "=r"(r[0]), "=r"(r[1]), "=r"(r[2]), "=r"(r[3]) : "r"(a));
}
__device__ __forceinline__ void ldsm4t(uint32_t r[4], uint32_t a) {
    asm volatile("ldmatrix.sync.aligned.m8n8.x4.trans.shared.b16 {%0,%1,%2,%3}, [%4];\n"
        : "=r"(r[0]), "=r"(r[1]), "=r"(r[2]), "=r"(r[3]) : "r"(a));
}
__device__ __forceinline__ void mma16816(float d[4], const uint32_t a[4], const uint32_t b[2]) {
    asm volatile("mma.sync.aligned.m16n8k16.row.col.f32.f16.f16.f32 "
        "{%0,%1,%2,%3}, {%4,%5,%6,%7}, {%8,%9}, {%0,%1,%2,%3};\n"
        : "+f"(d[0]), "+f"(d[1]), "+f"(d[2]), "+f"(d[3])
        : "r"(a[0]), "r"(a[1]), "r"(a[2]), "r"(a[3]), "r"(b[0]), "r"(b[1]));
}
__device__ __forceinline__ uint32_t packh2(float a, float b) {
    __half2 h = __floats2half2_rn(a, b);
    return *reinterpret_cast<uint32_t*>(&h);
}
#define CPA16(dst, src) \
    asm volatile("cp.async.cg.shared.global [%0], [%1], 16;" :: "r"(dst), "l"(src))
#define CPA_COMMIT() asm volatile("cp.async.commit_group;")

// ---------------------------------------------------------------------------
// W prep: fuse Wk|Wq|Wv -> g_wf[k][192] fp16 (row pad 200)
// ---------------------------------------------------------------------------
__global__ void wprep_kernel(const float* __restrict__ Wk,
                             const float* __restrict__ Wq,
                             const float* __restrict__ Wv)
{
    int idx = blockIdx.x*256 + threadIdx.x;       // over 1024*192
    int k = idx / 192, n = idx % 192;
    int m = n >> 6, h = n & 63;
    const float* W = (m == 0) ? Wk : (m == 1) ? Wq : Wv;
    g_wf[(size_t)k*200 + n] = __float2half_rn(W[(size_t)k*HH + h]);
}

// ---------------------------------------------------------------------------
// Projection: [16384 x 1024] x [1024 x 192]. 256 CTAs x 64 rows, 256 thr.
// K chunk = 64 (16 chunks): halves per-chunk overhead vs K=32.
// Dynamic smem 88064 B: xh 2x9216 @0, xl 2x9216 @18432, ws 2x25600 @36864.
// x: float4 LDG -> reg hi/lo convert -> STS (pipelined). W: cp.async 2-buf.
// ---------------------------------------------------------------------------
#define PROJ_SMEM 88064

__device__ __forceinline__ void w_stage64(char* wsb, int k0, int tid) {
    #pragma unroll
    for (int i = 0; i < 6; i++) {
        int j = tid + i*256;                      // 0..1535 = 64 rows x 24 grp
        int r = j / 24, c8 = (j % 24)*8;
        CPA16(smaddr(wsb + r*400 + c8*2), &g_wf[(size_t)(k0 + r)*200 + c8]);
    }
}

__global__ __launch_bounds__(256, 2) void proj_kernel(const float* __restrict__ x)
{
    extern __shared__ char sm[];
    const int tid = threadIdx.x;
    const int wid = tid >> 5, lane = tid & 31;
    const int wg = wid >> 2, w4 = wid & 3;
    const int row0 = blockIdx.x * 64;
    const int g = lane >> 3, rl = lane & 7;
    const int xr = tid >> 4;                      // 0..15
    const int xc = (tid & 15)*4;                  // 0..60

    float acc[12][4];
    #pragma unroll
    for (int j = 0; j < 12; j++)
        #pragma unroll
        for (int e = 0; e < 4; e++) acc[j][e] = 0.f;

    w_stage64(sm + 36864, 0, tid);
    CPA_COMMIT();
    float4 px[4];
    #pragma unroll
    for (int i = 0; i < 4; i++)
        px[i] = *(const float4*)&x[(size_t)(row0 + i*16 + xr)*CC + xc];

    #pragma unroll 1
    for (int c = 0; c < 16; c++) {
        const int buf = c & 1;
        char* xh  = sm + buf*9216;
        char* xl  = sm + 18432 + buf*9216;
        char* wsb = sm + 36864 + buf*25600;
        __syncthreads();                          // prev-chunk readers done
        #pragma unroll
        for (int i = 0; i < 4; i++) {             // STS chunk c (hi/lo split)
            int row = i*16 + xr;
            float4 v = px[i];
            __half hx = __float2half_rn(v.x), hy = __float2half_rn(v.y);
            __half hz = __float2half_rn(v.z), hw = __float2half_rn(v.w);
            *(uint2*)(xh + row*144 + xc*2) = make_uint2(
                *(uint32_t*)&(const __half2&)__halves2half2(hx, hy),
                *(uint32_t*)&(const __half2&)__halves2half2(hz, hw));
            *(uint2*)(xl + row*144 + xc*2) = make_uint2(
                packh2(v.x - __half2float(hx), v.y - __half2float(hy)),
                packh2(v.z - __half2float(hz), v.w - __half2float(hw)));
        }
        if (c + 1 < 16) {
            w_stage64(sm + 36864 + (buf ^ 1)*25600, (c+1)*64, tid);
            CPA_COMMIT();
            #pragma unroll
            for (int i = 0; i < 4; i++)
                px[i] = *(const float4*)
                    &x[(size_t)(row0 + i*16 + xr)*CC + (c+1)*64 + xc];
            asm volatile("cp.async.wait_group 1;");
        } else {
            asm volatile("cp.async.wait_group 0;");
        }
        __syncthreads();                          // chunk c staged

        #pragma unroll
        for (int sub = 0; sub < 4; sub++) {
            uint32_t ah[4], al[4];
            int ar = w4*16 + (lane & 15), ac = sub*16 + ((lane >> 4) << 3);
            ldsm4(ah, smaddr(xh + ar*144 + ac*2));
            ldsm4(al, smaddr(xl + ar*144 + ac*2));
            int br = sub*16 + (g & 1)*8 + rl;
            #pragma unroll
            for (int j = 0; j < 6; j++) {
                int bc = wg*96 + j*16 + (g >> 1)*8;
                uint32_t bh[4];
                ldsm4t(bh, smaddr(wsb + br*400 + bc*2));
                mma16816(acc[2*j],   ah, bh);
                mma16816(acc[2*j],   al, bh);
                mma16816(acc[2*j+1], ah, bh + 2);
                mma16816(acc[2*j+1], al, bh + 2);
            }
        }
    }

    // epilogue
    const int rl4 = lane >> 2, q2 = (lane & 3)*2;
    #pragma unroll
    for (int j = 0; j < 6; j++) {
        #pragma unroll
        for (int h = 0; h < 2; h++) {
            int n = wg*96 + j*16 + h*8 + q2;
            int m = n >> 6, hc = n & 63;
            #pragma unroll
            for (int er = 0; er < 2; er++) {
                float v0 = acc[2*j+h][er*2], v1 = acc[2*j+h][er*2+1];
                size_t off = (size_t)(row0 + w4*16 + rl4 + er*8)*HH + hc;
                if (m == 2) {
                    *(__half2*)&g_vh[off] = __floats2half2_rn(v0, v1);
                } else if (m == 0) {
                    *(__half2*)&g_kh[off] = __floats2half2_rn(v0, v1);
                } else {
                    v0 *= 0.125f; v1 *= 0.125f;
                    __half h0 = __float2half_rn(v0), h1 = __float2half_rn(v1);
                    *(__half2*)&g_qh[off] = __halves2half2(h0, h1);
                    *(__half2*)&g_ql[off] = __halves2half2(
                        __float2half_rn(v0 - __half2float(h0)),
                        __float2half_rn(v1 - __half2float(h1)));
                }
            }
        }
    }
}

// ---------------------------------------------------------------------------
// Flash attention, split-KV: CTA (qt, js) does kt = js, js+SPL, ... <= qt.
// ---------------------------------------------------------------------------
#define ATT_SMEM_BYTES ((4608*2 + 2*9216) * 2)

__device__ __forceinline__ void kv_prefetch(__half* sh, int buf, size_t gbase,
                                            int tid)
{
    __half* base = sh + 9216 + buf*9216;
    #pragma unroll
    for (int i = 0; i < 8; i++) {
        int j = tid + i*128;
        int surf = j >> 9, rc = j & 511;
        int r = rc >> 3, c = (rc & 7)*8;
        CPA16(smaddr(base + surf*4608 + r*72 + c),
              (surf ? g_vh : g_kh) + gbase + r*64 + c);
    }
}

__global__ __launch_bounds__(128) void attn_kernel()
{
    extern __shared__ __half sh[];
    __half* Qh = sh;
    __half* Ql = sh + 4608;

    const int tid = threadIdx.x;
    const int w = tid >> 5, lane = tid & 31;
    const int qt = NQT - 1 - ((int)blockIdx.x >> 2);
    const int js = blockIdx.x & 3;
    const int b = blockIdx.y;
    const int chunk = (b*NQT + qt)*SPL + js;
    float* po = g_pO + (size_t)chunk*4096;

    if (js > qt) {
        #pragma unroll
        for (int i = 0; i < 32; i++) po[tid + i*128] = 0.f;
        if (tid < 64) g_pML[chunk*64 + tid] = make_float2(-1e9f, 0.f);
        return;
    }

    const size_t kvb = (size_t)b*TT*HH;
    kv_prefetch(sh, 0, kvb + (size_t)js*64*HH, tid);
    CPA_COMMIT();

    {
        const size_t qb = kvb + (size_t)qt*64*HH;
        #pragma unroll
        for (int i = 0; i < 4; i++) {
            int idx = tid + i*128; int r = idx >> 3, c = (idx & 7)*8;
            *(int4*)&Qh[r*72 + c] = *(const int4*)&g_qh[qb + r*64 + c];
            *(int4*)&Ql[r*72 + c] = *(const int4*)&g_ql[qb + r*64 + c];
        }
    }
    __syncthreads();

    uint32_t aqh[4][4], aql[4][4];
    #pragma unroll
    for (int kc = 0; kc < 4; kc++) {
        int r = w*16 + (lane & 15), c = kc*16 + ((lane >> 4) << 3);
        ldsm4(aqh[kc], smaddr(&Qh[r*72 + c]));
        ldsm4(aql[kc], smaddr(&Ql[r*72 + c]));
    }

    float o[8][4];
    #pragma unroll
    for (int nt = 0; nt < 8; nt++)
        #pragma unroll
        for (int e = 0; e < 4; e++) o[nt][e] = 0.f;
    float m0 = -1e9f, m1 = -1e9f, l0 = 0.f, l1 = 0.f;

    #pragma unroll 1
    for (int kt = js; kt <= qt; kt += SPL) {
        __syncthreads();
        if (kt + SPL <= qt) {
            kv_prefetch(sh, ((kt - js) >> 2 & 1) ^ 1,
                        kvb + (size_t)(kt + SPL)*64*HH, tid);
            CPA_COMMIT();
            asm volatile("cp.async.wait_group 1;");
        } else {
            asm volatile("cp.async.wait_group 0;");
        }
        __syncthreads();

        __half* Khp = sh + 9216 + ((kt - js) >> 2 & 1)*9216;
        __half* Vsp = Khp + 4608;

        float s[8][4];
        #pragma unroll
        for (int nt = 0; nt < 8; nt++)
            #pragma unroll
            for (int e = 0; e < 4; e++) s[nt][e] = 0.f;
        const int g = lane >> 3, rl8 = lane & 7;
        #pragma unroll
        for (int kc = 0; kc < 4; kc++) {
            #pragma unroll
            for (int jj = 0; jj < 4; jj++) {
                int r = jj*16 + (g >> 1)*8 + rl8;
                int ccol = kc*16 + (g & 1)*8;
                uint32_t bh[4];
                ldsm4(bh, smaddr(&Khp[r*72 + ccol]));
                mma16816(s[2*jj],   aqh[kc], bh);
                mma16816(s[2*jj],   aql[kc], bh);
                mma16816(s[2*jj+1], aqh[kc], bh + 2);
                mma16816(s[2*jj+1], aql[kc], bh + 2);
            }
        }

        if (kt == qt) {
            int r0l = w*16 + (lane >> 2);
            int c0l = (lane & 3)*2;
            #pragma unroll
            for (int nt = 0; nt < 8; nt++) {
                int c = nt*8 + c0l;
                if (c     > r0l)     s[nt][0] = -1e9f;
                if (c + 1 > r0l)     s[nt][1] = -1e9f;
                if (c     > r0l + 8) s[nt][2] = -1e9f;
                if (c + 1 > r0l + 8) s[nt][3] = -1e9f;
            }
        }

        float rm0 = -1e9f, rm1 = -1e9f;
        #pragma unroll
        for (int nt = 0; nt < 8; nt++) {
            rm0 = fmaxf(rm0, fmaxf(s[nt][0], s[nt][1]));
            rm1 = fmaxf(rm1, fmaxf(s[nt][2], s[nt][3]));
        }
        rm0 = fmaxf(rm0, __shfl_xor_sync(0xffffffffu, rm0, 1));
        rm0 = fmaxf(rm0, __shfl_xor_sync(0xffffffffu, rm0, 2));
        rm1 = fmaxf(rm1, __shfl_xor_sync(0xffffffffu, rm1, 1));
        rm1 = fmaxf(rm1, __shfl_xor_sync(0xffffffffu, rm1, 2));
        float mn0 = fmaxf(m0, rm0), mn1 = fmaxf(m1, rm1);
        float corr0 = __expf(m0 - mn0), corr1 = __expf(m1 - mn1);
        m0 = mn0; m1 = mn1;
        float rs0 = 0.f, rs1 = 0.f;
        #pragma unroll
        for (int nt = 0; nt < 8; nt++) {
            s[nt][0] = __expf(s[nt][0] - mn0); rs0 += s[nt][0];
            s[nt][1] = __expf(s[nt][1] - mn0); rs0 += s[nt][1];
            s[nt][2] = __expf(s[nt][2] - mn1); rs1 += s[nt][2];
            s[nt][3] = __expf(s[nt][3] - mn1); rs1 += s[nt][3];
        }
        rs0 += __shfl_xor_sync(0xffffffffu, rs0, 1);
        rs0 += __shfl_xor_sync(0xffffffffu, rs0, 2);
        rs1 += __shfl_xor_sync(0xffffffffu, rs1, 1);
        rs1 += __shfl_xor_sync(0xffffffffu, rs1, 2);
        l0 = l0*corr0 + rs0;
        l1 = l1*corr1 + rs1;
        #pragma unroll
        for (int nt = 0; nt < 8; nt++) {
            o[nt][0] *= corr0; o[nt][1] *= corr0;
            o[nt][2] *= corr1; o[nt][3] *= corr1;
        }

        #pragma unroll
        for (int kc = 0; kc < 4; kc++) {
            uint32_t ap[4];
            ap[0] = packh2(s[2*kc][0],   s[2*kc][1]);
            ap[1] = packh2(s[2*kc][2],   s[2*kc][3]);
            ap[2] = packh2(s[2*kc+1][0], s[2*kc+1][1]);
            ap[3] = packh2(s[2*kc+1][2], s[2*kc+1][3]);
            #pragma unroll
            for (int jj = 0; jj < 4; jj++) {
                int r = kc*16 + (g & 1)*8 + rl8;
                int ccol = jj*16 + (g >> 1)*8;
                uint32_t vb[4];
                ldsm4t(vb, smaddr(&Vsp[r*72 + ccol]));
                mma16816(o[2*jj],   ap, vb);
                mma16816(o[2*jj+1], ap, vb + 2);
            }
        }
    }

    const int r0 = w*16 + (lane >> 2);
    #pragma unroll
    for (int nt = 0; nt < 8; nt++) {
        int c = nt*8 + (lane & 3)*2;
        *(float2*)&po[r0*64 + c]     = make_float2(o[nt][0], o[nt][1]);
        *(float2*)&po[(r0+8)*64 + c] = make_float2(o[nt][2], o[nt][3]);
    }
    if ((lane & 3) == 0) {
        g_pML[chunk*64 + r0]     = make_float2(m0, l0);
        g_pML[chunk*64 + r0 + 8] = make_float2(m1, l1);
    }
}

// ---------------------------------------------------------------------------
// Merge: 512 threads; thread handles rows r and r+32 (8 float4 + 8 float2
// independent loads front-batched for MLP).
// ---------------------------------------------------------------------------
__global__ __launch_bounds__(512) void merge_kernel(float* __restrict__ out)
{
    const int qt = blockIdx.x, b = blockIdx.y;
    const int tid = threadIdx.x;
    const int r = tid >> 4;                       // 0..31
    const int c4 = (tid & 15)*4;
    const int c0 = (b*NQT + qt)*SPL;

    float2 ml[2][SPL];
    float4 p[2][SPL];
    #pragma unroll
    for (int j = 0; j < SPL; j++) {
        ml[0][j] = g_pML[(c0 + j)*64 + r];
        ml[1][j] = g_pML[(c0 + j)*64 + r + 32];
        p[0][j] = *(const float4*)&g_pO[(size_t)(c0 + j)*4096 + r*64 + c4];
        p[1][j] = *(const float4*)&g_pO[(size_t)(c0 + j)*4096 + (r+32)*64 + c4];
    }
    #pragma unroll
    for (int h = 0; h < 2; h++) {
        float M = -1e30f;
        #pragma unroll
        for (int j = 0; j < SPL; j++) M = fmaxf(M, ml[h][j].x);
        float wsum = 0.f, wj[SPL];
        #pragma unroll
        for (int j = 0; j < SPL; j++) {
            wj[j] = __expf(ml[h][j].x - M);
            wsum += wj[j]*ml[h][j].y;
        }
        const float inv = 1.0f/wsum;
        float4 a = make_float4(0.f, 0.f, 0.f, 0.f);
        #pragma unroll
        for (int j = 0; j < SPL; j++) {
            a.x += wj[j]*p[h][j].x; a.y += wj[j]*p[h][j].y;
            a.z += wj[j]*p[h][j].z; a.w += wj[j]*p[h][j].w;
        }
        a.x *= inv; a.y *= inv; a.z *= inv; a.w *= inv;
        *(float4*)&out[((size_t)b*TT + qt*64 + r + h*32)*HH + c4] = a;
    }
}

extern "C" void kernel_launch(void* const* d_in, const int* in_sizes, int n_in,
                              void* d_out, int out_size) {
    const float* x  = (const float*)d_in[0];
    const float* Wk = (const float*)d_in[1];
    const float* Wq = (const float*)d_in[2];
    const float* Wv = (const float*)d_in[3];
    float* out = (float*)d_out;

    static int init = 0;
    if (!init) {
        cudaFuncSetAttribute(proj_kernel,
            cudaFuncAttributeMaxDynamicSharedMemorySize, PROJ_SMEM);
        cudaFuncSetAttribute(attn_kernel,
            cudaFuncAttributeMaxDynamicSharedMemorySize, ATT_SMEM_BYTES);
        init = 1;
    }

    wprep_kernel<<<768, 256>>>(Wk, Wq, Wv);
    proj_kernel<<<(BB*TT)/64, 256, PROJ_SMEM>>>(x);
    attn_kernel<<<dim3(NQT*SPL, BB), 128, ATT_SMEM_BYTES>>>();
    merge_kernel<<<dim3(NQT, BB), 512>>>(out);
}

// round 11
// speedup vs baseline: 1.1942x; 1.0575x over previous
#include <cuda_runtime.h>
#include <cuda_fp16.h>
#include <cstdint>

#define BB 8
#define TT 2048
#define CC 1024
#define HH 64
#define NQT 32
#define SPL 4

__device__ __align__(16) __half g_qh[BB*TT*HH];
__device__ __align__(16) __half g_ql[BB*TT*HH];
__device__ __align__(16) __half g_kh[BB*TT*HH];
__device__ __align__(16) __half g_vh[BB*TT*HH];
// fused fp16 W rows k, 192 cols (pad 200). Column layout: K | V[0:32] | Q | V[32:64]
__device__ __align__(16) __half g_wf[CC*200];
__device__ __align__(16) __half g_pOh[BB*NQT*SPL*64*64];   // fp16 partials
__device__ float2 g_pML[BB*NQT*SPL*64];                    // (m, l)

__device__ __forceinline__ uint32_t smaddr(const void* p) {
    return (uint32_t)__cvta_generic_to_shared(p);
}
__device__ __forceinline__ void ldsm4(uint32_t r[4], uint32_t a) {
    asm volatile("ldmatrix.sync.aligned.m8n8.x4.shared.b16 {%0,%1,%2,%3}, [%4];\n"
        : "=r"(r[0]), "=r"(r[1]), "=r"(r[2]), "=r"(r[3]) : "r"(a));
}
__device__ __forceinline__ void ldsm4t(uint32_t r[4], uint32_t a) {
    asm volatile("ldmatrix.sync.aligned.m8n8.x4.trans.shared.b16 {%0,%1,%2,%3}, [%4];\n"
        : "=r"(r[0]), "=r"(r[1]), "=r"(r[2]), "=r"(r[3]) : "r"(a));
}
__device__ __forceinline__ void mma16816(float d[4], const uint32_t a[4], const uint32_t b[2]) {
    asm volatile("mma.sync.aligned.m16n8k16.row.col.f32.f16.f16.f32 "
        "{%0,%1,%2,%3}, {%4,%5,%6,%7}, {%8,%9}, {%0,%1,%2,%3};\n"
        : "+f"(d[0]), "+f"(d[1]), "+f"(d[2]), "+f"(d[3])
        : "r"(a[0]), "r"(a[1]), "r"(a[2]), "r"(a[3]), "r"(b[0]), "r"(b[1]));
}
__device__ __forceinline__ uint32_t packh2(float a, float b) {
    __half2 h = __floats2half2_rn(a, b);
    return *reinterpret_cast<uint32_t*>(&h);
}
#define CPA16(dst, src) \
    asm volatile("cp.async.cg.shared.global [%0], [%1], 16;" :: "r"(dst), "l"(src))
#define CPA_COMMIT() asm volatile("cp.async.commit_group;")

// ---------------------------------------------------------------------------
// W prep: fuse into g_wf[k][192] with layout K | V[0:32] | Q | V[32:64]
// ---------------------------------------------------------------------------
__global__ void wprep_kernel(const float* __restrict__ Wk,
                             const float* __restrict__ Wq,
                             const float* __restrict__ Wv)
{
    int idx = blockIdx.x*256 + threadIdx.x;       // over 1024*192
    int k = idx / 192, n = idx % 192;
    const float* W;
    int h;
    if (n < 64)       { W = Wk; h = n; }
    else if (n < 96)  { W = Wv; h = n - 64; }
    else if (n < 160) { W = Wq; h = n - 96; }
    else              { W = Wv; h = n - 128; }
    g_wf[(size_t)k*200 + n] = __float2half_rn(W[(size_t)k*HH + h]);
}

// ---------------------------------------------------------------------------
// Projection: [16384 x 1024] x [1024 x 192]. 256 CTAs x 64 rows, 256 thr.
// K chunk = 64. x hi/lo split; lo-mma ONLY for K/Q tiles (j<4 per warp-group).
// Dynamic smem 88064 B: xh 2x9216 @0, xl 2x9216 @18432, ws 2x25600 @36864.
// ---------------------------------------------------------------------------
#define PROJ_SMEM 88064

__device__ __forceinline__ void w_stage64(char* wsb, int k0, int tid) {
    #pragma unroll
    for (int i = 0; i < 6; i++) {
        int j = tid + i*256;                      // 64 rows x 24 groups
        int r = j / 24, c8 = (j % 24)*8;
        CPA16(smaddr(wsb + r*400 + c8*2), &g_wf[(size_t)(k0 + r)*200 + c8]);
    }
}

__global__ __launch_bounds__(256, 2) void proj_kernel(const float* __restrict__ x)
{
    extern __shared__ char sm[];
    const int tid = threadIdx.x;
    const int wid = tid >> 5, lane = tid & 31;
    const int wg = wid >> 2, w4 = wid & 3;
    const int row0 = blockIdx.x * 64;
    const int g = lane >> 3, rl = lane & 7;
    const int xr = tid >> 4;                      // 0..15
    const int xc = (tid & 15)*4;                  // 0..60

    float acc[12][4];
    #pragma unroll
    for (int j = 0; j < 12; j++)
        #pragma unroll
        for (int e = 0; e < 4; e++) acc[j][e] = 0.f;

    w_stage64(sm + 36864, 0, tid);
    CPA_COMMIT();
    float4 px[4];
    #pragma unroll
    for (int i = 0; i < 4; i++)
        px[i] = *(const float4*)&x[(size_t)(row0 + i*16 + xr)*CC + xc];

    #pragma unroll 1
    for (int c = 0; c < 16; c++) {
        const int buf = c & 1;
        char* xh  = sm + buf*9216;
        char* xl  = sm + 18432 + buf*9216;
        char* wsb = sm + 36864 + buf*25600;
        __syncthreads();
        #pragma unroll
        for (int i = 0; i < 4; i++) {
            int row = i*16 + xr;
            float4 v = px[i];
            __half hx = __float2half_rn(v.x), hy = __float2half_rn(v.y);
            __half hz = __float2half_rn(v.z), hw = __float2half_rn(v.w);
            *(uint2*)(xh + row*144 + xc*2) = make_uint2(
                *(uint32_t*)&(const __half2&)__halves2half2(hx, hy),
                *(uint32_t*)&(const __half2&)__halves2half2(hz, hw));
            *(uint2*)(xl + row*144 + xc*2) = make_uint2(
                packh2(v.x - __half2float(hx), v.y - __half2float(hy)),
                packh2(v.z - __half2float(hz), v.w - __half2float(hw)));
        }
        if (c + 1 < 16) {
            w_stage64(sm + 36864 + (buf ^ 1)*25600, (c+1)*64, tid);
            CPA_COMMIT();
            #pragma unroll
            for (int i = 0; i < 4; i++)
                px[i] = *(const float4*)
                    &x[(size_t)(row0 + i*16 + xr)*CC + (c+1)*64 + xc];
            asm volatile("cp.async.wait_group 1;");
        } else {
            asm volatile("cp.async.wait_group 0;");
        }
        __syncthreads();

        #pragma unroll
        for (int sub = 0; sub < 4; sub++) {
            uint32_t ah[4], al[4];
            int ar = w4*16 + (lane & 15), ac = sub*16 + ((lane >> 4) << 3);
            ldsm4(ah, smaddr(xh + ar*144 + ac*2));
            ldsm4(al, smaddr(xl + ar*144 + ac*2));
            int br = sub*16 + (g & 1)*8 + rl;
            #pragma unroll
            for (int j = 0; j < 6; j++) {
                int bc = wg*96 + j*16 + (g >> 1)*8;
                uint32_t bh[4];
                ldsm4t(bh, smaddr(wsb + br*400 + bc*2));
                mma16816(acc[2*j],   ah, bh);
                mma16816(acc[2*j+1], ah, bh + 2);
                if (j < 4) {                       // lo term: K/Q tiles only
                    mma16816(acc[2*j],   al, bh);
                    mma16816(acc[2*j+1], al, bh + 2);
                }
            }
        }
    }

    // epilogue (layout: K | V[0:32] | Q | V[32:64])
    const int rl4 = lane >> 2, q2 = (lane & 3)*2;
    #pragma unroll
    for (int j = 0; j < 6; j++) {
        #pragma unroll
        for (int h = 0; h < 2; h++) {
            int n = wg*96 + j*16 + h*8 + q2;
            #pragma unroll
            for (int er = 0; er < 2; er++) {
                float v0 = acc[2*j+h][er*2], v1 = acc[2*j+h][er*2+1];
                size_t roff = (size_t)(row0 + w4*16 + rl4 + er*8)*HH;
                if (n < 64) {
                    *(__half2*)&g_kh[roff + n] = __floats2half2_rn(v0, v1);
                } else if (n < 96) {
                    *(__half2*)&g_vh[roff + n - 64] = __floats2half2_rn(v0, v1);
                } else if (n < 160) {
                    v0 *= 0.125f; v1 *= 0.125f;
                    __half h0 = __float2half_rn(v0), h1 = __float2half_rn(v1);
                    *(__half2*)&g_qh[roff + n - 96] = __halves2half2(h0, h1);
                    *(__half2*)&g_ql[roff + n - 96] = __halves2half2(
                        __float2half_rn(v0 - __half2float(h0)),
                        __float2half_rn(v1 - __half2float(h1)));
                } else {
                    *(__half2*)&g_vh[roff + n - 128] = __floats2half2_rn(v0, v1);
                }
            }
        }
    }
}

// ---------------------------------------------------------------------------
// Flash attention, split-KV: CTA (qt, js) does kt = js, js+SPL, ... <= qt.
// Partials written fp16.
// ---------------------------------------------------------------------------
#define ATT_SMEM_BYTES ((4608*2 + 2*9216) * 2)

__device__ __forceinline__ void kv_prefetch(__half* sh, int buf, size_t gbase,
                                            int tid)
{
    __half* base = sh + 9216 + buf*9216;
    #pragma unroll
    for (int i = 0; i < 8; i++) {
        int j = tid + i*128;
        int surf = j >> 9, rc = j & 511;
        int r = rc >> 3, c = (rc & 7)*8;
        CPA16(smaddr(base + surf*4608 + r*72 + c),
              (surf ? g_vh : g_kh) + gbase + r*64 + c);
    }
}

__global__ __launch_bounds__(128) void attn_kernel()
{
    extern __shared__ __half sh[];
    __half* Qh = sh;
    __half* Ql = sh + 4608;

    const int tid = threadIdx.x;
    const int w = tid >> 5, lane = tid & 31;
    const int qt = NQT - 1 - ((int)blockIdx.x >> 2);
    const int js = blockIdx.x & 3;
    const int b = blockIdx.y;
    const int chunk = (b*NQT + qt)*SPL + js;
    __half* poh = g_pOh + (size_t)chunk*4096;

    if (js > qt) {
        #pragma unroll
        for (int i = 0; i < 16; i++) ((uint32_t*)poh)[tid + i*128] = 0u;
        if (tid < 64) g_pML[chunk*64 + tid] = make_float2(-1e9f, 0.f);
        return;
    }

    const size_t kvb = (size_t)b*TT*HH;
    kv_prefetch(sh, 0, kvb + (size_t)js*64*HH, tid);
    CPA_COMMIT();

    {
        const size_t qb = kvb + (size_t)qt*64*HH;
        #pragma unroll
        for (int i = 0; i < 4; i++) {
            int idx = tid + i*128; int r = idx >> 3, c = (idx & 7)*8;
            *(int4*)&Qh[r*72 + c] = *(const int4*)&g_qh[qb + r*64 + c];
            *(int4*)&Ql[r*72 + c] = *(const int4*)&g_ql[qb + r*64 + c];
        }
    }
    __syncthreads();

    uint32_t aqh[4][4], aql[4][4];
    #pragma unroll
    for (int kc = 0; kc < 4; kc++) {
        int r = w*16 + (lane & 15), c = kc*16 + ((lane >> 4) << 3);
        ldsm4(aqh[kc], smaddr(&Qh[r*72 + c]));
        ldsm4(aql[kc], smaddr(&Ql[r*72 + c]));
    }

    float o[8][4];
    #pragma unroll
    for (int nt = 0; nt < 8; nt++)
        #pragma unroll
        for (int e = 0; e < 4; e++) o[nt][e] = 0.f;
    float m0 = -1e9f, m1 = -1e9f, l0 = 0.f, l1 = 0.f;

    #pragma unroll 1
    for (int kt = js; kt <= qt; kt += SPL) {
        __syncthreads();
        if (kt + SPL <= qt) {
            kv_prefetch(sh, ((kt - js) >> 2 & 1) ^ 1,
                        kvb + (size_t)(kt + SPL)*64*HH, tid);
            CPA_COMMIT();
            asm volatile("cp.async.wait_group 1;");
        } else {
            asm volatile("cp.async.wait_group 0;");
        }
        __syncthreads();

        __half* Khp = sh + 9216 + ((kt - js) >> 2 & 1)*9216;
        __half* Vsp = Khp + 4608;

        float s[8][4];
        #pragma unroll
        for (int nt = 0; nt < 8; nt++)
            #pragma unroll
            for (int e = 0; e < 4; e++) s[nt][e] = 0.f;
        const int g = lane >> 3, rl8 = lane & 7;
        #pragma unroll
        for (int kc = 0; kc < 4; kc++) {
            #pragma unroll
            for (int jj = 0; jj < 4; jj++) {
                int r = jj*16 + (g >> 1)*8 + rl8;
                int ccol = kc*16 + (g & 1)*8;
                uint32_t bh[4];
                ldsm4(bh, smaddr(&Khp[r*72 + ccol]));
                mma16816(s[2*jj],   aqh[kc], bh);
                mma16816(s[2*jj],   aql[kc], bh);
                mma16816(s[2*jj+1], aqh[kc], bh + 2);
                mma16816(s[2*jj+1], aql[kc], bh + 2);
            }
        }

        if (kt == qt) {
            int r0l = w*16 + (lane >> 2);
            int c0l = (lane & 3)*2;
            #pragma unroll
            for (int nt = 0; nt < 8; nt++) {
                int c = nt*8 + c0l;
                if (c     > r0l)     s[nt][0] = -1e9f;
                if (c + 1 > r0l)     s[nt][1] = -1e9f;
                if (c     > r0l + 8) s[nt][2] = -1e9f;
                if (c + 1 > r0l + 8) s[nt][3] = -1e9f;
            }
        }

        float rm0 = -1e9f, rm1 = -1e9f;
        #pragma unroll
        for (int nt = 0; nt < 8; nt++) {
            rm0 = fmaxf(rm0, fmaxf(s[nt][0], s[nt][1]));
            rm1 = fmaxf(rm1, fmaxf(s[nt][2], s[nt][3]));
        }
        rm0 = fmaxf(rm0, __shfl_xor_sync(0xffffffffu, rm0, 1));
        rm0 = fmaxf(rm0, __shfl_xor_sync(0xffffffffu, rm0, 2));
        rm1 = fmaxf(rm1, __shfl_xor_sync(0xffffffffu, rm1, 1));
        rm1 = fmaxf(rm1, __shfl_xor_sync(0xffffffffu, rm1, 2));
        float mn0 = fmaxf(m0, rm0), mn1 = fmaxf(m1, rm1);
        float corr0 = __expf(m0 - mn0), corr1 = __expf(m1 - mn1);
        m0 = mn0; m1 = mn1;
        float rs0 = 0.f, rs1 = 0.f;
        #pragma unroll
        for (int nt = 0; nt < 8; nt++) {
            s[nt][0] = __expf(s[nt][0] - mn0); rs0 += s[nt][0];
            s[nt][1] = __expf(s[nt][1] - mn0); rs0 += s[nt][1];
            s[nt][2] = __expf(s[nt][2] - mn1); rs1 += s[nt][2];
            s[nt][3] = __expf(s[nt][3] - mn1); rs1 += s[nt][3];
        }
        rs0 += __shfl_xor_sync(0xffffffffu, rs0, 1);
        rs0 += __shfl_xor_sync(0xffffffffu, rs0, 2);
        rs1 += __shfl_xor_sync(0xffffffffu, rs1, 1);
        rs1 += __shfl_xor_sync(0xffffffffu, rs1, 2);
        l0 = l0*corr0 + rs0;
        l1 = l1*corr1 + rs1;
        #pragma unroll
        for (int nt = 0; nt < 8; nt++) {
            o[nt][0] *= corr0; o[nt][1] *= corr0;
            o[nt][2] *= corr1; o[nt][3] *= corr1;
        }

        #pragma unroll
        for (int kc = 0; kc < 4; kc++) {
            uint32_t ap[4];
            ap[0] = packh2(s[2*kc][0],   s[2*kc][1]);
            ap[1] = packh2(s[2*kc][2],   s[2*kc][3]);
            ap[2] = packh2(s[2*kc+1][0], s[2*kc+1][1]);
            ap[3] = packh2(s[2*kc+1][2], s[2*kc+1][3]);
            #pragma unroll
            for (int jj = 0; jj < 4; jj++) {
                int r = kc*16 + (g & 1)*8 + rl8;
                int ccol = jj*16 + (g >> 1)*8;
                uint32_t vb[4];
                ldsm4t(vb, smaddr(&Vsp[r*72 + ccol]));
                mma16816(o[2*jj],   ap, vb);
                mma16816(o[2*jj+1], ap, vb + 2);
            }
        }
    }

    const int r0 = w*16 + (lane >> 2);
    #pragma unroll
    for (int nt = 0; nt < 8; nt++) {
        int c = nt*8 + (lane & 3)*2;
        *(uint32_t*)&poh[r0*64 + c]     = packh2(o[nt][0], o[nt][1]);
        *(uint32_t*)&poh[(r0+8)*64 + c] = packh2(o[nt][2], o[nt][3]);
    }
    if ((lane & 3) == 0) {
        g_pML[chunk*64 + r0]     = make_float2(m0, l0);
        g_pML[chunk*64 + r0 + 8] = make_float2(m1, l1);
    }
}

// ---------------------------------------------------------------------------
// Merge: fp16 partials. 512 threads; thread = (row, 8-col group).
// ---------------------------------------------------------------------------
__global__ __launch_bounds__(512) void merge_kernel(float* __restrict__ out)
{
    const int qt = blockIdx.x, b = blockIdx.y;
    const int tid = threadIdx.x;
    const int r = tid >> 3;                       // 0..63
    const int c8 = (tid & 7)*8;
    const int c0 = (b*NQT + qt)*SPL;

    float2 ml[SPL];
    uint4 ph[SPL];
    #pragma unroll
    for (int j = 0; j < SPL; j++) {
        ml[j] = g_pML[(c0 + j)*64 + r];
        ph[j] = *(const uint4*)&g_pOh[(size_t)(c0 + j)*4096 + r*64 + c8];
    }
    float M = -1e30f;
    #pragma unroll
    for (int j = 0; j < SPL; j++) M = fmaxf(M, ml[j].x);
    float wsum = 0.f, wj[SPL];
    #pragma unroll
    for (int j = 0; j < SPL; j++) {
        wj[j] = __expf(ml[j].x - M);
        wsum += wj[j]*ml[j].y;
    }
    const float inv = 1.0f/wsum;

    float a[8];
    #pragma unroll
    for (int i = 0; i < 8; i++) a[i] = 0.f;
    #pragma unroll
    for (int j = 0; j < SPL; j++) {
        const uint32_t* u = (const uint32_t*)&ph[j];
        #pragma unroll
        for (int p = 0; p < 4; p++) {
            float2 v = __half22float2(*(const __half2*)&u[p]);
            a[2*p]   += wj[j]*v.x;
            a[2*p+1] += wj[j]*v.y;
        }
    }
    float4 o0 = make_float4(a[0]*inv, a[1]*inv, a[2]*inv, a[3]*inv);
    float4 o1 = make_float4(a[4]*inv, a[5]*inv, a[6]*inv, a[7]*inv);
    size_t off = ((size_t)b*TT + qt*64 + r)*HH + c8;
    *(float4*)&out[off]     = o0;
    *(float4*)&out[off + 4] = o1;
}

extern "C" void kernel_launch(void* const* d_in, const int* in_sizes, int n_in,
                              void* d_out, int out_size) {
    const float* x  = (const float*)d_in[0];
    const float* Wk = (const float*)d_in[1];
    const float* Wq = (const float*)d_in[2];
    const float* Wv = (const float*)d_in[3];
    float* out = (float*)d_out;

    static int init = 0;
    if (!init) {
        cudaFuncSetAttribute(proj_kernel,
            cudaFuncAttributeMaxDynamicSharedMemorySize, PROJ_SMEM);
        cudaFuncSetAttribute(attn_kernel,
            cudaFuncAttributeMaxDynamicSharedMemorySize, ATT_SMEM_BYTES);
        init = 1;
    }

    wprep_kernel<<<768, 256>>>(Wk, Wq, Wv);
    proj_kernel<<<(BB*TT)/64, 256, PROJ_SMEM>>>(x);
    attn_kernel<<<dim3(NQT*SPL, BB), 128, ATT_SMEM_BYTES>>>();
    merge_kernel<<<dim3(NQT, BB), 512>>>(out);
}

// round 12
// speedup vs baseline: 1.2346x; 1.0338x over previous
#include <cuda_runtime.h>
#include <cuda_fp16.h>
#include <cstdint>

#define BB 8
#define TT 2048
#define CC 1024
#define HH 64
#define NQT 32
#define SPL 4

__device__ __align__(16) __half g_qh[BB*TT*HH];
__device__ __align__(16) __half g_ql[BB*TT*HH];
__device__ __align__(16) __half g_kh[BB*TT*HH];
__device__ __align__(16) __half g_vh[BB*TT*HH];
// fused fp16 W rows k, 192 cols (pad 200).
// Layout: K[0:32] | Q[0:32] | V[0:32] | K[32:64] | Q[32:64] | V[32:64]
__device__ __align__(16) __half g_wf[CC*200];
__device__ __align__(16) __half g_pOh[BB*NQT*SPL*64*64];   // fp16 partials
__device__ float2 g_pML[BB*NQT*SPL*64];                    // (m, l)

__device__ __forceinline__ uint32_t smaddr(const void* p) {
    return (uint32_t)__cvta_generic_to_shared(p);
}
__device__ __forceinline__ void ldsm4(uint32_t r[4], uint32_t a) {
    asm volatile("ldmatrix.sync.aligned.m8n8.x4.shared.b16 {%0,%1,%2,%3}, [%4];\n"
        : "=r"(r[0]), "=r"(r[1]), "=r"(r[2]), "=r"(r[3]) : "r"(a));
}
__device__ __forceinline__ void ldsm4t(uint32_t r[4], uint32_t a) {
    asm volatile("ldmatrix.sync.aligned.m8n8.x4.trans.shared.b16 {%0,%1,%2,%3}, [%4];\n"
        : "=r"(r[0]), "=r"(r[1]), "=r"(r[2]), "=r"(r[3]) : "r"(a));
}
__device__ __forceinline__ void mma16816(float d[4], const uint32_t a[4], const uint32_t b[2]) {
    asm volatile("mma.sync.aligned.m16n8k16.row.col.f32.f16.f16.f32 "
        "{%0,%1,%2,%3}, {%4,%5,%6,%7}, {%8,%9}, {%0,%1,%2,%3};\n"
        : "+f"(d[0]), "+f"(d[1]), "+f"(d[2]), "+f"(d[3])
        : "r"(a[0]), "r"(a[1]), "r"(a[2]), "r"(a[3]), "r"(b[0]), "r"(b[1]));
}
__device__ __forceinline__ uint32_t packh2(float a, float b) {
    __half2 h = __floats2half2_rn(a, b);
    return *reinterpret_cast<uint32_t*>(&h);
}
#define CPA16(dst, src) \
    asm volatile("cp.async.cg.shared.global [%0], [%1], 16;" :: "r"(dst), "l"(src))
#define CPA_COMMIT() asm volatile("cp.async.commit_group;")

// ---------------------------------------------------------------------------
// W prep: layout K[0:32]|Q[0:32]|V[0:32]|K[32:64]|Q[32:64]|V[32:64]
// ---------------------------------------------------------------------------
__global__ void wprep_kernel(const float* __restrict__ Wk,
                             const float* __restrict__ Wq,
                             const float* __restrict__ Wv)
{
    int idx = blockIdx.x*256 + threadIdx.x;       // over 1024*192
    int k = idx / 192, n = idx % 192;
    int wgp = n / 96, r = n % 96;
    int type = r >> 5;                            // 0=K 1=Q 2=V
    int h = wgp*32 + (r & 31);
    const float* W = (type == 0) ? Wk : (type == 1) ? Wq : Wv;
    g_wf[(size_t)k*200 + n] = __float2half_rn(W[(size_t)k*HH + h]);
}

// ---------------------------------------------------------------------------
// Projection: [16384 x 1024] x [1024 x 192]. 256 CTAs x 64 rows, 256 thr.
// K chunk = 64. x hi/lo split; lo-mma ONLY for Q tiles (j==2,3 per wg).
// Dynamic smem 88064 B: xh 2x9216 @0, xl 2x9216 @18432, ws 2x25600 @36864.
// ---------------------------------------------------------------------------
#define PROJ_SMEM 88064

__device__ __forceinline__ void w_stage64(char* wsb, int k0, int tid) {
    #pragma unroll
    for (int i = 0; i < 6; i++) {
        int j = tid + i*256;                      // 64 rows x 24 groups
        int r = j / 24, c8 = (j % 24)*8;
        CPA16(smaddr(wsb + r*400 + c8*2), &g_wf[(size_t)(k0 + r)*200 + c8]);
    }
}

__global__ __launch_bounds__(256, 2) void proj_kernel(const float* __restrict__ x)
{
    extern __shared__ char sm[];
    const int tid = threadIdx.x;
    const int wid = tid >> 5, lane = tid & 31;
    const int wg = wid >> 2, w4 = wid & 3;
    const int row0 = blockIdx.x * 64;
    const int g = lane >> 3, rl = lane & 7;
    const int xr = tid >> 4;                      // 0..15
    const int xc = (tid & 15)*4;                  // 0..60

    float acc[12][4];
    #pragma unroll
    for (int j = 0; j < 12; j++)
        #pragma unroll
        for (int e = 0; e < 4; e++) acc[j][e] = 0.f;

    w_stage64(sm + 36864, 0, tid);
    CPA_COMMIT();
    float4 px[4];
    #pragma unroll
    for (int i = 0; i < 4; i++)
        px[i] = *(const float4*)&x[(size_t)(row0 + i*16 + xr)*CC + xc];

    #pragma unroll 1
    for (int c = 0; c < 16; c++) {
        const int buf = c & 1;
        char* xh  = sm + buf*9216;
        char* xl  = sm + 18432 + buf*9216;
        char* wsb = sm + 36864 + buf*25600;
        __syncthreads();
        #pragma unroll
        for (int i = 0; i < 4; i++) {
            int row = i*16 + xr;
            float4 v = px[i];
            __half hx = __float2half_rn(v.x), hy = __float2half_rn(v.y);
            __half hz = __float2half_rn(v.z), hw = __float2half_rn(v.w);
            *(uint2*)(xh + row*144 + xc*2) = make_uint2(
                *(uint32_t*)&(const __half2&)__halves2half2(hx, hy),
                *(uint32_t*)&(const __half2&)__halves2half2(hz, hw));
            *(uint2*)(xl + row*144 + xc*2) = make_uint2(
                packh2(v.x - __half2float(hx), v.y - __half2float(hy)),
                packh2(v.z - __half2float(hz), v.w - __half2float(hw)));
        }
        if (c + 1 < 16) {
            w_stage64(sm + 36864 + (buf ^ 1)*25600, (c+1)*64, tid);
            CPA_COMMIT();
            #pragma unroll
            for (int i = 0; i < 4; i++)
                px[i] = *(const float4*)
                    &x[(size_t)(row0 + i*16 + xr)*CC + (c+1)*64 + xc];
            asm volatile("cp.async.wait_group 1;");
        } else {
            asm volatile("cp.async.wait_group 0;");
        }
        __syncthreads();

        #pragma unroll
        for (int sub = 0; sub < 4; sub++) {
            uint32_t ah[4], al[4];
            int ar = w4*16 + (lane & 15), ac = sub*16 + ((lane >> 4) << 3);
            ldsm4(ah, smaddr(xh + ar*144 + ac*2));
            ldsm4(al, smaddr(xl + ar*144 + ac*2));
            int br = sub*16 + (g & 1)*8 + rl;
            #pragma unroll
            for (int j = 0; j < 6; j++) {
                int bc = wg*96 + j*16 + (g >> 1)*8;
                uint32_t bh[4];
                ldsm4t(bh, smaddr(wsb + br*400 + bc*2));
                mma16816(acc[2*j],   ah, bh);
                mma16816(acc[2*j+1], ah, bh + 2);
                if ((j >> 1) == 1) {               // lo term: Q tiles only
                    mma16816(acc[2*j],   al, bh);
                    mma16816(acc[2*j+1], al, bh + 2);
                }
            }
        }
    }

    // epilogue (layout per wg: K[32] | Q[32] | V[32], h = wg*32 + (r&31))
    const int rl4 = lane >> 2, q2 = (lane & 3)*2;
    #pragma unroll
    for (int j = 0; j < 6; j++) {
        #pragma unroll
        for (int h2 = 0; h2 < 2; h2++) {
            int r = j*16 + h2*8 + q2;              // 0..95 within wg
            int type = r >> 5;
            int hc = wg*32 + (r & 31);
            #pragma unroll
            for (int er = 0; er < 2; er++) {
                float v0 = acc[2*j+h2][er*2], v1 = acc[2*j+h2][er*2+1];
                size_t roff = (size_t)(row0 + w4*16 + rl4 + er*8)*HH + hc;
                if (type == 0) {
                    *(__half2*)&g_kh[roff] = __floats2half2_rn(v0, v1);
                } else if (type == 2) {
                    *(__half2*)&g_vh[roff] = __floats2half2_rn(v0, v1);
                } else {
                    v0 *= 0.125f; v1 *= 0.125f;
                    __half h0 = __float2half_rn(v0), h1 = __float2half_rn(v1);
                    *(__half2*)&g_qh[roff] = __halves2half2(h0, h1);
                    *(__half2*)&g_ql[roff] = __halves2half2(
                        __float2half_rn(v0 - __half2float(h0)),
                        __float2half_rn(v1 - __half2float(h1)));
                }
            }
        }
    }
}

// ---------------------------------------------------------------------------
// Flash attention, split-KV: CTA (qt, js) does kt = js, js+SPL, ... <= qt.
// Partials fp16. Empty splits (js > qt) exit; merge zeroes them arithmetically.
// ---------------------------------------------------------------------------
#define ATT_SMEM_BYTES ((4608*2 + 2*9216) * 2)

__device__ __forceinline__ void kv_prefetch(__half* sh, int buf, size_t gbase,
                                            int tid)
{
    __half* base = sh + 9216 + buf*9216;
    #pragma unroll
    for (int i = 0; i < 8; i++) {
        int j = tid + i*128;
        int surf = j >> 9, rc = j & 511;
        int r = rc >> 3, c = (rc & 7)*8;
        CPA16(smaddr(base + surf*4608 + r*72 + c),
              (surf ? g_vh : g_kh) + gbase + r*64 + c);
    }
}

__global__ __launch_bounds__(128) void attn_kernel()
{
    extern __shared__ __half sh[];
    __half* Qh = sh;
    __half* Ql = sh + 4608;

    const int tid = threadIdx.x;
    const int w = tid >> 5, lane = tid & 31;
    const int qt = NQT - 1 - ((int)blockIdx.x >> 2);
    const int js = blockIdx.x & 3;
    const int b = blockIdx.y;
    const int chunk = (b*NQT + qt)*SPL + js;
    __half* poh = g_pOh + (size_t)chunk*4096;

    if (js > qt) return;                          // merge handles empty splits

    const size_t kvb = (size_t)b*TT*HH;
    kv_prefetch(sh, 0, kvb + (size_t)js*64*HH, tid);
    CPA_COMMIT();

    {
        const size_t qb = kvb + (size_t)qt*64*HH;
        #pragma unroll
        for (int i = 0; i < 4; i++) {
            int idx = tid + i*128; int r = idx >> 3, c = (idx & 7)*8;
            *(int4*)&Qh[r*72 + c] = *(const int4*)&g_qh[qb + r*64 + c];
            *(int4*)&Ql[r*72 + c] = *(const int4*)&g_ql[qb + r*64 + c];
        }
    }
    __syncthreads();

    uint32_t aqh[4][4], aql[4][4];
    #pragma unroll
    for (int kc = 0; kc < 4; kc++) {
        int r = w*16 + (lane & 15), c = kc*16 + ((lane >> 4) << 3);
        ldsm4(aqh[kc], smaddr(&Qh[r*72 + c]));
        ldsm4(aql[kc], smaddr(&Ql[r*72 + c]));
    }

    float o[8][4];
    #pragma unroll
    for (int nt = 0; nt < 8; nt++)
        #pragma unroll
        for (int e = 0; e < 4; e++) o[nt][e] = 0.f;
    float m0 = -1e9f, m1 = -1e9f, l0 = 0.f, l1 = 0.f;

    #pragma unroll 1
    for (int kt = js; kt <= qt; kt += SPL) {
        __syncthreads();
        if (kt + SPL <= qt) {
            kv_prefetch(sh, ((kt - js) >> 2 & 1) ^ 1,
                        kvb + (size_t)(kt + SPL)*64*HH, tid);
            CPA_COMMIT();
            asm volatile("cp.async.wait_group 1;");
        } else {
            asm volatile("cp.async.wait_group 0;");
        }
        __syncthreads();

        __half* Khp = sh + 9216 + ((kt - js) >> 2 & 1)*9216;
        __half* Vsp = Khp + 4608;

        float s[8][4];
        #pragma unroll
        for (int nt = 0; nt < 8; nt++)
            #pragma unroll
            for (int e = 0; e < 4; e++) s[nt][e] = 0.f;
        const int g = lane >> 3, rl8 = lane & 7;
        #pragma unroll
        for (int kc = 0; kc < 4; kc++) {
            #pragma unroll
            for (int jj = 0; jj < 4; jj++) {
                int r = jj*16 + (g >> 1)*8 + rl8;
                int ccol = kc*16 + (g & 1)*8;
                uint32_t bh[4];
                ldsm4(bh, smaddr(&Khp[r*72 + ccol]));
                mma16816(s[2*jj],   aqh[kc], bh);
                mma16816(s[2*jj],   aql[kc], bh);
                mma16816(s[2*jj+1], aqh[kc], bh + 2);
                mma16816(s[2*jj+1], aql[kc], bh + 2);
            }
        }

        if (kt == qt) {
            int r0l = w*16 + (lane >> 2);
            int c0l = (lane & 3)*2;
            #pragma unroll
            for (int nt = 0; nt < 8; nt++) {
                int c = nt*8 + c0l;
                if (c     > r0l)     s[nt][0] = -1e9f;
                if (c + 1 > r0l)     s[nt][1] = -1e9f;
                if (c     > r0l + 8) s[nt][2] = -1e9f;
                if (c + 1 > r0l + 8) s[nt][3] = -1e9f;
            }
        }

        float rm0 = -1e9f, rm1 = -1e9f;
        #pragma unroll
        for (int nt = 0; nt < 8; nt++) {
            rm0 = fmaxf(rm0, fmaxf(s[nt][0], s[nt][1]));
            rm1 = fmaxf(rm1, fmaxf(s[nt][2], s[nt][3]));
        }
        rm0 = fmaxf(rm0, __shfl_xor_sync(0xffffffffu, rm0, 1));
        rm0 = fmaxf(rm0, __shfl_xor_sync(0xffffffffu, rm0, 2));
        rm1 = fmaxf(rm1, __shfl_xor_sync(0xffffffffu, rm1, 1));
        rm1 = fmaxf(rm1, __shfl_xor_sync(0xffffffffu, rm1, 2));
        float mn0 = fmaxf(m0, rm0), mn1 = fmaxf(m1, rm1);
        float corr0 = __expf(m0 - mn0), corr1 = __expf(m1 - mn1);
        m0 = mn0; m1 = mn1;
        float rs0 = 0.f, rs1 = 0.f;
        #pragma unroll
        for (int nt = 0; nt < 8; nt++) {
            s[nt][0] = __expf(s[nt][0] - mn0); rs0 += s[nt][0];
            s[nt][1] = __expf(s[nt][1] - mn0); rs0 += s[nt][1];
            s[nt][2] = __expf(s[nt][2] - mn1); rs1 += s[nt][2];
            s[nt][3] = __expf(s[nt][3] - mn1); rs1 += s[nt][3];
        }
        rs0 += __shfl_xor_sync(0xffffffffu, rs0, 1);
        rs0 += __shfl_xor_sync(0xffffffffu, rs0, 2);
        rs1 += __shfl_xor_sync(0xffffffffu, rs1, 1);
        rs1 += __shfl_xor_sync(0xffffffffu, rs1, 2);
        l0 = l0*corr0 + rs0;
        l1 = l1*corr1 + rs1;
        #pragma unroll
        for (int nt = 0; nt < 8; nt++) {
            o[nt][0] *= corr0; o[nt][1] *= corr0;
            o[nt][2] *= corr1; o[nt][3] *= corr1;
        }

        #pragma unroll
        for (int kc = 0; kc < 4; kc++) {
            uint32_t ap[4];
            ap[0] = packh2(s[2*kc][0],   s[2*kc][1]);
            ap[1] = packh2(s[2*kc][2],   s[2*kc][3]);
            ap[2] = packh2(s[2*kc+1][0], s[2*kc+1][1]);
            ap[3] = packh2(s[2*kc+1][2], s[2*kc+1][3]);
            #pragma unroll
            for (int jj = 0; jj < 4; jj++) {
                int r = kc*16 + (g & 1)*8 + rl8;
                int ccol = jj*16 + (g >> 1)*8;
                uint32_t vb[4];
                ldsm4t(vb, smaddr(&Vsp[r*72 + ccol]));
                mma16816(o[2*jj],   ap, vb);
                mma16816(o[2*jj+1], ap, vb + 2);
            }
        }
    }

    const int r0 = w*16 + (lane >> 2);
    #pragma unroll
    for (int nt = 0; nt < 8; nt++) {
        int c = nt*8 + (lane & 3)*2;
        *(uint32_t*)&poh[r0*64 + c]     = packh2(o[nt][0], o[nt][1]);
        *(uint32_t*)&poh[(r0+8)*64 + c] = packh2(o[nt][2], o[nt][3]);
    }
    if ((lane & 3) == 0) {
        g_pML[chunk*64 + r0]     = make_float2(m0, l0);
        g_pML[chunk*64 + r0 + 8] = make_float2(m1, l1);
    }
}

// ---------------------------------------------------------------------------
// Merge: fp16 partials; splits j > qt treated as empty (w = 0, nothing read).
// 512 threads; thread = (row, 8-col group).
// ---------------------------------------------------------------------------
__global__ __launch_bounds__(512) void merge_kernel(float* __restrict__ out)
{
    const int qt = blockIdx.x, b = blockIdx.y;
    const int tid = threadIdx.x;
    const int r = tid >> 3;                       // 0..63
    const int c8 = (tid & 7)*8;
    const int c0 = (b*NQT + qt)*SPL;

    float2 ml[SPL];
    uint4 ph[SPL];
    #pragma unroll
    for (int j = 0; j < SPL; j++) {
        if (j <= qt) {
            ml[j] = g_pML[(c0 + j)*64 + r];
            ph[j] = *(const uint4*)&g_pOh[(size_t)(c0 + j)*4096 + r*64 + c8];
        } else {
            ml[j] = make_float2(-1e30f, 0.f);
            ph[j] = make_uint4(0u, 0u, 0u, 0u);
        }
    }
    float M = -1e30f;
    #pragma unroll
    for (int j = 0; j < SPL; j++) M = fmaxf(M, ml[j].x);
    float wsum = 0.f, wj[SPL];
    #pragma unroll
    for (int j = 0; j < SPL; j++) {
        wj[j] = __expf(ml[j].x - M);
        wsum += wj[j]*ml[j].y;
    }
    const float inv = 1.0f/wsum;

    float a[8];
    #pragma unroll
    for (int i = 0; i < 8; i++) a[i] = 0.f;
    #pragma unroll
    for (int j = 0; j < SPL; j++) {
        const uint32_t* u = (const uint32_t*)&ph[j];
        #pragma unroll
        for (int p = 0; p < 4; p++) {
            float2 v = __half22float2(*(const __half2*)&u[p]);
            a[2*p]   += wj[j]*v.x;
            a[2*p+1] += wj[j]*v.y;
        }
    }
    float4 o0 = make_float4(a[0]*inv, a[1]*inv, a[2]*inv, a[3]*inv);
    float4 o1 = make_float4(a[4]*inv, a[5]*inv, a[6]*inv, a[7]*inv);
    size_t off = ((size_t)b*TT + qt*64 + r)*HH + c8;
    *(float4*)&out[off]     = o0;
    *(float4*)&out[off + 4] = o1;
}

extern "C" void kernel_launch(void* const* d_in, const int* in_sizes, int n_in,
                              void* d_out, int out_size) {
    const float* x  = (const float*)d_in[0];
    const float* Wk = (const float*)d_in[1];
    const float* Wq = (const float*)d_in[2];
    const float* Wv = (const float*)d_in[3];
    float* out = (float*)d_out;

    static int init = 0;
    if (!init) {
        cudaFuncSetAttribute(proj_kernel,
            cudaFuncAttributeMaxDynamicSharedMemorySize, PROJ_SMEM);
        cudaFuncSetAttribute(attn_kernel,
            cudaFuncAttributeMaxDynamicSharedMemorySize, ATT_SMEM_BYTES);
        init = 1;
    }

    wprep_kernel<<<768, 256>>>(Wk, Wq, Wv);
    proj_kernel<<<(BB*TT)/64, 256, PROJ_SMEM>>>(x);
    attn_kernel<<<dim3(NQT*SPL, BB), 128, ATT_SMEM_BYTES>>>();
    merge_kernel<<<dim3(NQT, BB), 512>>>(out);
}

// round 15
// speedup vs baseline: 1.4314x; 1.1594x over previous
#include <cuda_runtime.h>
#include <cuda_fp16.h>
#include <cstdint>

#define BB 8
#define TT 2048
#define CC 1024
#define HH 64
#define NQT 32
#define SPL 4
#define QSCALE 0.1803368801111601f   // 0.125 * log2(e)

__device__ __align__(16) __half g_qh[BB*TT*HH];
__device__ __align__(16) __half g_kh[BB*TT*HH];
__device__ __align__(16) __half g_vh[BB*TT*HH];
// fused fp16 W rows k, 192 cols (pad 200).
// Layout: K[0:32] | Q[0:32] | V[0:32] | K[32:64] | Q[32:64] | V[32:64]
__device__ __align__(16) __half g_wf[CC*200];
__device__ __align__(16) __half g_pOh[BB*NQT*SPL*64*64];   // fp16 partials
__device__ float2 g_pML[BB*NQT*SPL*64];                    // (m, l) in log2 domain

__device__ __forceinline__ float ex2(float x) {
    float y;
    asm("ex2.approx.f32 %0, %1;" : "=f"(y) : "f"(x));
    return y;
}
__device__ __forceinline__ uint32_t smaddr(const void* p) {
    return (uint32_t)__cvta_generic_to_shared(p);
}
__device__ __forceinline__ void ldsm4(uint32_t r[4], uint32_t a) {
    asm volatile("ldmatrix.sync.aligned.m8n8.x4.shared.b16 {%0,%1,%2,%3}, [%4];\n"
        : "=r"(r[0]), "=r"(r[1]), "=r"(r[2]), "=r"(r[3]) : "r"(a));
}
__device__ __forceinline__ void ldsm4t(uint32_t r[4], uint32_t a) {
    asm volatile("ldmatrix.sync.aligned.m8n8.x4.trans.shared.b16 {%0,%1,%2,%3}, [%4];\n"
        : "=r"(r[0]), "=r"(r[1]), "=r"(r[2]), "=r"(r[3]) : "r"(a));
}
__device__ __forceinline__ void mma16816(float d[4], const uint32_t a[4], const uint32_t b[2]) {
    asm volatile("mma.sync.aligned.m16n8k16.row.col.f32.f16.f16.f32 "
        "{%0,%1,%2,%3}, {%4,%5,%6,%7}, {%8,%9}, {%0,%1,%2,%3};\n"
        : "+f"(d[0]), "+f"(d[1]), "+f"(d[2]), "+f"(d[3])
        : "r"(a[0]), "r"(a[1]), "r"(a[2]), "r"(a[3]), "r"(b[0]), "r"(b[1]));
}
__device__ __forceinline__ uint32_t packh2(float a, float b) {
    __half2 h = __floats2half2_rn(a, b);
    return *reinterpret_cast<uint32_t*>(&h);
}
#define CPA16(dst, src) \
    asm volatile("cp.async.cg.shared.global [%0], [%1], 16;" :: "r"(dst), "l"(src))
#define CPA_COMMIT() asm volatile("cp.async.commit_group;")

// ---------------------------------------------------------------------------
// W prep: layout K[0:32]|Q[0:32]|V[0:32]|K[32:64]|Q[32:64]|V[32:64]
// ---------------------------------------------------------------------------
__global__ void wprep_kernel(const float* __restrict__ Wk,
                             const float* __restrict__ Wq,
                             const float* __restrict__ Wv)
{
    int idx = blockIdx.x*256 + threadIdx.x;       // over 1024*192
    int k = idx / 192, n = idx % 192;
    int wgp = n / 96, r = n % 96;
    int type = r >> 5;                            // 0=K 1=Q 2=V
    int h = wgp*32 + (r & 31);
    const float* W = (type == 0) ? Wk : (type == 1) ? Wq : Wv;
    g_wf[(size_t)k*200 + n] = __float2half_rn(W[(size_t)k*HH + h]);
}

// ---------------------------------------------------------------------------
// Projection: [16384 x 1024] x [1024 x 192]. 256 CTAs x 64 rows, 256 thr.
// K chunk = 64. Pure fp16 path (no compensation; error absorbed by softmax).
// Dynamic smem 69632 B: xh 2x9216 @0, ws 2x25600 @18432.
// ---------------------------------------------------------------------------
#define PROJ_SMEM 69632

__device__ __forceinline__ void w_stage64(char* wsb, int k0, int tid) {
    #pragma unroll
    for (int i = 0; i < 6; i++) {
        int j = tid + i*256;                      // 64 rows x 24 groups
        int r = j / 24, c8 = (j % 24)*8;
        CPA16(smaddr(wsb + r*400 + c8*2), &g_wf[(size_t)(k0 + r)*200 + c8]);
    }
}

__global__ __launch_bounds__(256, 2) void proj_kernel(const float* __restrict__ x)
{
    extern __shared__ char sm[];
    const int tid = threadIdx.x;
    const int wid = tid >> 5, lane = tid & 31;
    const int wg = wid >> 2, w4 = wid & 3;
    const int row0 = blockIdx.x * 64;
    const int g = lane >> 3, rl = lane & 7;
    const int xr = tid >> 4;                      // 0..15
    const int xc = (tid & 15)*4;                  // 0..60

    float acc[12][4];
    #pragma unroll
    for (int j = 0; j < 12; j++)
        #pragma unroll
        for (int e = 0; e < 4; e++) acc[j][e] = 0.f;

    w_stage64(sm + 18432, 0, tid);
    CPA_COMMIT();
    float4 px[4];
    #pragma unroll
    for (int i = 0; i < 4; i++)
        px[i] = *(const float4*)&x[(size_t)(row0 + i*16 + xr)*CC + xc];

    #pragma unroll 1
    for (int c = 0; c < 16; c++) {
        const int buf = c & 1;
        char* xh  = sm + buf*9216;
        char* wsb = sm + 18432 + buf*25600;
        __syncthreads();                          // prev-chunk readers done
        #pragma unroll
        for (int i = 0; i < 4; i++) {             // STS chunk c (fp16)
            int row = i*16 + xr;
            float4 v = px[i];
            *(uint2*)(xh + row*144 + xc*2) = make_uint2(
                packh2(v.x, v.y), packh2(v.z, v.w));
        }
        if (c + 1 < 16) {
            w_stage64(sm + 18432 + (buf ^ 1)*25600, (c+1)*64, tid);
            CPA_COMMIT();
            #pragma unroll
            for (int i = 0; i < 4; i++)
                px[i] = *(const float4*)
                    &x[(size_t)(row0 + i*16 + xr)*CC + (c+1)*64 + xc];
            asm volatile("cp.async.wait_group 1;");
        } else {
            asm volatile("cp.async.wait_group 0;");
        }
        __syncthreads();                          // chunk c staged

        #pragma unroll
        for (int sub = 0; sub < 4; sub++) {
            uint32_t ah[4];
            int ar = w4*16 + (lane & 15), ac = sub*16 + ((lane >> 4) << 3);
            ldsm4(ah, smaddr(xh + ar*144 + ac*2));
            int br = sub*16 + (g & 1)*8 + rl;
            #pragma unroll
            for (int j = 0; j < 6; j++) {
                int bc = wg*96 + j*16 + (g >> 1)*8;
                uint32_t bh[4];
                ldsm4t(bh, smaddr(wsb + br*400 + bc*2));
                mma16816(acc[2*j],   ah, bh);
                mma16816(acc[2*j+1], ah, bh + 2);
            }
        }
    }

    // epilogue (layout per wg: K[32] | Q[32] | V[32], h = wg*32 + (r&31))
    const int rl4 = lane >> 2, q2 = (lane & 3)*2;
    #pragma unroll
    for (int j = 0; j < 6; j++) {
        #pragma unroll
        for (int h2 = 0; h2 < 2; h2++) {
            int r = j*16 + h2*8 + q2;              // 0..95 within wg
            int type = r >> 5;
            int hc = wg*32 + (r & 31);
            #pragma unroll
            for (int er = 0; er < 2; er++) {
                float v0 = acc[2*j+h2][er*2], v1 = acc[2*j+h2][er*2+1];
                size_t roff = (size_t)(row0 + w4*16 + rl4 + er*8)*HH + hc;
                if (type == 0) {
                    *(__half2*)&g_kh[roff] = __floats2half2_rn(v0, v1);
                } else if (type == 2) {
                    *(__half2*)&g_vh[roff] = __floats2half2_rn(v0, v1);
                } else {
                    *(__half2*)&g_qh[roff] =
                        __floats2half2_rn(v0*QSCALE, v1*QSCALE);
                }
            }
        }
    }
}

// ---------------------------------------------------------------------------
// Flash attention, split-KV: CTA (qt, js) does kt = js, js+SPL, ... <= qt.
// q pre-scaled by 0.125*log2(e); softmax in exp2 domain. Partials fp16.
// smem: Qh [64][72] @0 (9216 B), KV bufs @4608 halfs.
// ---------------------------------------------------------------------------
#define ATT_SMEM_BYTES ((4608 + 2*9216) * 2)      // 46080

__device__ __forceinline__ void kv_prefetch(__half* sh, int buf, size_t gbase,
                                            int tid)
{
    __half* base = sh + 4608 + buf*9216;
    #pragma unroll
    for (int i = 0; i < 8; i++) {
        int j = tid + i*128;
        int surf = j >> 9, rc = j & 511;
        int r = rc >> 3, c = (rc & 7)*8;
        CPA16(smaddr(base + surf*4608 + r*72 + c),
              (surf ? g_vh : g_kh) + gbase + r*64 + c);
    }
}

__global__ __launch_bounds__(128) void attn_kernel()
{
    extern __shared__ __half sh[];
    __half* Qh = sh;

    const int tid = threadIdx.x;
    const int w = tid >> 5, lane = tid & 31;
    const int qt = NQT - 1 - ((int)blockIdx.x >> 2);
    const int js = blockIdx.x & 3;
    const int b = blockIdx.y;
    const int chunk = (b*NQT + qt)*SPL + js;
    __half* poh = g_pOh + (size_t)chunk*4096;

    if (js > qt) return;                          // merge handles empty splits

    const size_t kvb = (size_t)b*TT*HH;
    kv_prefetch(sh, 0, kvb + (size_t)js*64*HH, tid);
    CPA_COMMIT();

    {
        const size_t qb = kvb + (size_t)qt*64*HH;
        #pragma unroll
        for (int i = 0; i < 4; i++) {
            int idx = tid + i*128; int r = idx >> 3, c = (idx & 7)*8;
            *(int4*)&Qh[r*72 + c] = *(const int4*)&g_qh[qb + r*64 + c];
        }
    }
    __syncthreads();

    uint32_t aq[4][4];
    #pragma unroll
    for (int kc = 0; kc < 4; kc++) {
        int r = w*16 + (lane & 15), c = kc*16 + ((lane >> 4) << 3);
        ldsm4(aq[kc], smaddr(&Qh[r*72 + c]));
    }

    float o[8][4];
    #pragma unroll
    for (int nt = 0; nt < 8; nt++)
        #pragma unroll
        for (int e = 0; e < 4; e++) o[nt][e] = 0.f;
    float m0 = -1e9f, m1 = -1e9f, l0 = 0.f, l1 = 0.f;

    #pragma unroll 1
    for (int kt = js; kt <= qt; kt += SPL) {
        __syncthreads();
        if (kt + SPL <= qt) {
            kv_prefetch(sh, ((kt - js) >> 2 & 1) ^ 1,
                        kvb + (size_t)(kt + SPL)*64*HH, tid);
            CPA_COMMIT();
            asm volatile("cp.async.wait_group 1;");
        } else {
            asm volatile("cp.async.wait_group 0;");
        }
        __syncthreads();

        __half* Khp = sh + 4608 + ((kt - js) >> 2 & 1)*9216;
        __half* Vsp = Khp + 4608;

        float s[8][4];
        #pragma unroll
        for (int nt = 0; nt < 8; nt++)
            #pragma unroll
            for (int e = 0; e < 4; e++) s[nt][e] = 0.f;
        const int g = lane >> 3, rl8 = lane & 7;
        #pragma unroll
        for (int kc = 0; kc < 4; kc++) {
            #pragma unroll
            for (int jj = 0; jj < 4; jj++) {
                int r = jj*16 + (g >> 1)*8 + rl8;
                int ccol = kc*16 + (g & 1)*8;
                uint32_t bh[4];
                ldsm4(bh, smaddr(&Khp[r*72 + ccol]));
                mma16816(s[2*jj],   aq[kc], bh);
                mma16816(s[2*jj+1], aq[kc], bh + 2);
            }
        }

        if (kt == qt) {
            int r0l = w*16 + (lane >> 2);
            int c0l = (lane & 3)*2;
            #pragma unroll
            for (int nt = 0; nt < 8; nt++) {
                int c = nt*8 + c0l;
                if (c     > r0l)     s[nt][0] = -1e9f;
                if (c + 1 > r0l)     s[nt][1] = -1e9f;
                if (c     > r0l + 8) s[nt][2] = -1e9f;
                if (c + 1 > r0l + 8) s[nt][3] = -1e9f;
            }
        }

        float rm0 = -1e9f, rm1 = -1e9f;
        #pragma unroll
        for (int nt = 0; nt < 8; nt++) {
            rm0 = fmaxf(rm0, fmaxf(s[nt][0], s[nt][1]));
            rm1 = fmaxf(rm1, fmaxf(s[nt][2], s[nt][3]));
        }
        rm0 = fmaxf(rm0, __shfl_xor_sync(0xffffffffu, rm0, 1));
        rm0 = fmaxf(rm0, __shfl_xor_sync(0xffffffffu, rm0, 2));
        rm1 = fmaxf(rm1, __shfl_xor_sync(0xffffffffu, rm1, 1));
        rm1 = fmaxf(rm1, __shfl_xor_sync(0xffffffffu, rm1, 2));
        float mn0 = fmaxf(m0, rm0), mn1 = fmaxf(m1, rm1);
        float corr0 = ex2(m0 - mn0), corr1 = ex2(m1 - mn1);
        m0 = mn0; m1 = mn1;
        float rs0 = 0.f, rs1 = 0.f;
        #pragma unroll
        for (int nt = 0; nt < 8; nt++) {
            s[nt][0] = ex2(s[nt][0] - mn0); rs0 += s[nt][0];
            s[nt][1] = ex2(s[nt][1] - mn0); rs0 += s[nt][1];
            s[nt][2] = ex2(s[nt][2] - mn1); rs1 += s[nt][2];
            s[nt][3] = ex2(s[nt][3] - mn1); rs1 += s[nt][3];
        }
        rs0 += __shfl_xor_sync(0xffffffffu, rs0, 1);
        rs0 += __shfl_xor_sync(0xffffffffu, rs0, 2);
        rs1 += __shfl_xor_sync(0xffffffffu, rs1, 1);
        rs1 += __shfl_xor_sync(0xffffffffu, rs1, 2);
        l0 = l0*corr0 + rs0;
        l1 = l1*corr1 + rs1;
        #pragma unroll
        for (int nt = 0; nt < 8; nt++) {
            o[nt][0] *= corr0; o[nt][1] *= corr0;
            o[nt][2] *= corr1; o[nt][3] *= corr1;
        }

        #pragma unroll
        for (int kc = 0; kc < 4; kc++) {
            uint32_t ap[4];
            ap[0] = packh2(s[2*kc][0],   s[2*kc][1]);
            ap[1] = packh2(s[2*kc][2],   s[2*kc][3]);
            ap[2] = packh2(s[2*kc+1][0], s[2*kc+1][1]);
            ap[3] = packh2(s[2*kc+1][2], s[2*kc+1][3]);
            #pragma unroll
            for (int jj = 0; jj < 4; jj++) {
                int r = kc*16 + (g & 1)*8 + rl8;
                int ccol = jj*16 + (g >> 1)*8;
                uint32_t vb[4];
                ldsm4t(vb, smaddr(&Vsp[r*72 + ccol]));
                mma16816(o[2*jj],   ap, vb);
                mma16816(o[2*jj+1], ap, vb + 2);
            }
        }
    }

    const int r0 = w*16 + (lane >> 2);
    #pragma unroll
    for (int nt = 0; nt < 8; nt++) {
        int c = nt*8 + (lane & 3)*2;
        *(uint32_t*)&poh[r0*64 + c]     = packh2(o[nt][0], o[nt][1]);
        *(uint32_t*)&poh[(r0+8)*64 + c] = packh2(o[nt][2], o[nt][3]);
    }
    if ((lane & 3) == 0) {
        g_pML[chunk*64 + r0]     = make_float2(m0, l0);
        g_pML[chunk*64 + r0 + 8] = make_float2(m1, l1);
    }
}

// ---------------------------------------------------------------------------
// Merge: fp16 partials, exp2 domain; splits j > qt are empty (weight 0).
// 256 threads; thread = (row, 16-col group): 8 uint4 + 4 float2 loads batched.
// ---------------------------------------------------------------------------
__global__ __launch_bounds__(256) void merge_kernel(float* __restrict__ out)
{
    const int qt = blockIdx.x, b = blockIdx.y;
    const int tid = threadIdx.x;
    const int r = tid >> 2;                       // 0..63
    const int c16 = (tid & 3)*16;
    const int c0 = (b*NQT + qt)*SPL;

    float2 ml[SPL];
    uint4 ph[SPL][2];
    #pragma unroll
    for (int j = 0; j < SPL; j++) {
        if (j <= qt) {
            ml[j] = g_pML[(c0 + j)*64 + r];
            const uint4* p = (const uint4*)&g_pOh[(size_t)(c0 + j)*4096 + r*64 + c16];
            ph[j][0] = p[0];
            ph[j][1] = p[1];
        } else {
            ml[j] = make_float2(-1e30f, 0.f);
            ph[j][0] = ph[j][1] = make_uint4(0u, 0u, 0u, 0u);
        }
    }
    float M = -1e30f;
    #pragma unroll
    for (int j = 0; j < SPL; j++) M = fmaxf(M, ml[j].x);
    float wsum = 0.f, wj[SPL];
    #pragma unroll
    for (int j = 0; j < SPL; j++) {
        wj[j] = ex2(ml[j].x - M);
        wsum += wj[j]*ml[j].y;
    }
    const float inv = 1.0f/wsum;

    float a[16];
    #pragma unroll
    for (int i = 0; i < 16; i++) a[i] = 0.f;
    #pragma unroll
    for (int j = 0; j < SPL; j++) {
        #pragma unroll
        for (int half = 0; half < 2; half++) {
            const uint32_t* u = (const uint32_t*)&ph[j][half];
            #pragma unroll
            for (int p = 0; p < 4; p++) {
                float2 v = __half22float2(*(const __half2*)&u[p]);
                a[half*8 + 2*p]   += wj[j]*v.x;
                a[half*8 + 2*p+1] += wj[j]*v.y;
            }
        }
    }
    size_t off = ((size_t)b*TT + qt*64 + r)*HH + c16;
    #pragma unroll
    for (int qd = 0; qd < 4; qd++) {
        *(float4*)&out[off + qd*4] = make_float4(
            a[qd*4]*inv, a[qd*4+1]*inv, a[qd*4+2]*inv, a[qd*4+3]*inv);
    }
}

extern "C" void kernel_launch(void* const* d_in, const int* in_sizes, int n_in,
                              void* d_out, int out_size) {
    const float* x  = (const float*)d_in[0];
    const float* Wk = (const float*)d_in[1];
    const float* Wq = (const float*)d_in[2];
    const float* Wv = (const float*)d_in[3];
    float* out = (float*)d_out;

    static int init = 0;
    if (!init) {
        cudaFuncSetAttribute(proj_kernel,
            cudaFuncAttributeMaxDynamicSharedMemorySize, PROJ_SMEM);
        cudaFuncSetAttribute(attn_kernel,
            cudaFuncAttributeMaxDynamicSharedMemorySize, ATT_SMEM_BYTES);
        init = 1;
    }

    wprep_kernel<<<768, 256>>>(Wk, Wq, Wv);
    proj_kernel<<<(BB*TT)/64, 256, PROJ_SMEM>>>(x);
    attn_kernel<<<dim3(NQT*SPL, BB), 128, ATT_SMEM_BYTES>>>();
    merge_kernel<<<dim3(NQT, BB), 256>>>(out);
}